// round 13
// baseline (speedup 1.0000x reference)
#include <cuda_runtime.h>
#include <cuda_fp16.h>
#include <cstdint>
#include <cstddef>

// Problem constants
#define H_    4
#define DM_   512
#define DK_   128
#define B_    1024
#define LQ_   32
#define LK_   64

// ---------------- scratch (device globals; no allocation allowed) ----------
__device__ float g_wqeff[H_ * DM_];
__device__ float g_wkeff[H_ * DM_];
__device__ float g_attn[(size_t)H_ * B_ * LQ_ * LK_];            //  33 MB (fallback)
__device__ __align__(16) __half g_vh[(size_t)B_ * LK_ * DM_];    //  67 MB (v fp16)
__device__ __align__(16) __half g_wvh[DM_ * DM_];                // 0.5 MB
__device__ __align__(16) __half g_fcwh[DM_ * DM_];               // 0.5 MB
__device__ __align__(16) __half g_oh[(size_t)B_ * LQ_ * DM_];    //  33 MB (oattn fp16)
__device__ __align__(16) __half g_fch[(size_t)B_ * LQ_ * DM_];   //  33 MB (fc out fp16)
__device__ int   g_maskmode;

__device__ __forceinline__ uint32_t smem_u32(const void* p) {
    uint32_t a;
    asm("{ .reg .u64 t; cvta.to.shared.u64 t, %1; cvt.u32.u64 %0, t; }"
        : "=r"(a) : "l"(p));
    return a;
}
__device__ __forceinline__ void cp_async16(uint32_t dst, const void* src) {
    asm volatile("cp.async.cg.shared.global [%0], [%1], 16;" :: "r"(dst), "l"(src));
}
#define CP_COMMIT() asm volatile("cp.async.commit_group;" ::: "memory")
#define CP_WAIT1()  asm volatile("cp.async.wait_group 1;" ::: "memory")

__device__ __forceinline__ void ldsm_x4(uint32_t& r0, uint32_t& r1, uint32_t& r2,
                                        uint32_t& r3, uint32_t addr) {
    asm volatile("ldmatrix.sync.aligned.m8n8.x4.shared.b16 {%0,%1,%2,%3}, [%4];"
                 : "=r"(r0), "=r"(r1), "=r"(r2), "=r"(r3) : "r"(addr));
}
__device__ __forceinline__ void ldsm_x4_t(uint32_t& r0, uint32_t& r1, uint32_t& r2,
                                          uint32_t& r3, uint32_t addr) {
    asm volatile("ldmatrix.sync.aligned.m8n8.x4.trans.shared.b16 {%0,%1,%2,%3}, [%4];"
                 : "=r"(r0), "=r"(r1), "=r"(r2), "=r"(r3) : "r"(addr));
}
__device__ __forceinline__ void mma_f16(float* c,
                                        uint32_t a0, uint32_t a1, uint32_t a2, uint32_t a3,
                                        uint32_t b0, uint32_t b1) {
    asm volatile("mma.sync.aligned.m16n8k16.row.col.f32.f16.f16.f32 "
                 "{%0,%1,%2,%3}, {%4,%5,%6,%7}, {%8,%9}, {%0,%1,%2,%3};"
                 : "+f"(c[0]), "+f"(c[1]), "+f"(c[2]), "+f"(c[3])
                 : "r"(a0), "r"(a1), "r"(a2), "r"(a3), "r"(b0), "r"(b1));
}

__device__ __forceinline__ bool load_mask(const void* m, int mode, size_t idx) {
    if (mode == 2) return ((const float*)m)[idx] != 0.0f;
    if (mode == 1) return ((const int*)m)[idx] != 0;
    return ((const unsigned char*)m)[idx] != 0u;
}

// ====================== GEMM tiling constants ===============================
// 256 threads = 8 warps (2m x 4n), warp tile 64x64. CTA tile 128x256. 1 CTA/SM.
#define BM 128
#define BN 256
#define BK 32
#define NKT (DM_ / BK)        // 16
#define STG 3
#define ROWB 80               // bytes per smem row (64 data + 16 pad)
#define ROWS_PER_STAGE (BM + BN)            // 384
#define STG_BYTES (ROWS_PER_STAGE * ROWB)   // 30720 B
#define GEMM_SMEM (STG * STG_BYTES)         // 92160 B
// O-phase smem layout (reuses stage memory after mainloop)
#define VPS 264               // vp_s stride in halfs (528 B/row)
#define PS  72                // P_s stride in halfs
#define P_S_HOFF (128 * VPS)  // halfs offset of P_s (67584 B); P_s = 2*64*72*2 = 18432 B
// fp32 attn prefetch (beyond pipeline stages; persistent): 2 heads x 64 x 64 f32
#define PF_OFF  GEMM_SMEM                   // 92160
#define AV_SMEM (GEMM_SMEM + 32768)         // 124928 B

// ---- shared mainloop pieces -------------------------------------------------
#define GEMM_PROLOG()                                                          \
    const __half* gptr[6];                                                     \
    uint32_t doff[6];                                                          \
    _Pragma("unroll")                                                          \
    for (int i = 0; i < 6; i++) {                                              \
        const int c = tid + 256 * i;                                           \
        const int row = c >> 2, ch = c & 3;                                    \
        gptr[i] = (row < BM ? A + (size_t)(bm + row) * DM_                     \
                            : W + (size_t)(bn + row - BM) * DM_) + ch * 8;     \
        doff[i] = (uint32_t)(row * ROWB + ch * 16);                            \
    }                                                                          \
    auto load_tile = [&](int kt, int s) {                                      \
        const uint32_t base = sbase + (uint32_t)(s * STG_BYTES);               \
        _Pragma("unroll")                                                      \
        for (int i = 0; i < 6; i++)                                            \
            cp_async16(base + doff[i], gptr[i] + kt * BK);                     \
    };                                                                         \
    const uint32_t aOff = (uint32_t)(wm * 64 + (lane & 15)) * ROWB             \
                        + (uint32_t)(lane >> 4) * 16;                          \
    const uint32_t bOff = (uint32_t)(BM + wn * 64 + (lane & 7)                 \
                        + ((lane >> 4) << 3)) * ROWB                           \
                        + (uint32_t)((lane >> 3) & 1) * 16;

#define GEMM_MAINLOOP(ACC)                                                     \
    int stage = 0;                                                             \
    for (int kt = 0; kt < NKT; kt++) {                                         \
        CP_WAIT1();                                                            \
        __syncthreads();                                                       \
        if (kt + 2 < NKT) load_tile(kt + 2, (kt + 2) % STG);                   \
        CP_COMMIT();                                                           \
        const uint32_t sa = sbase + (uint32_t)(stage * STG_BYTES);             \
        _Pragma("unroll")                                                      \
        for (int ks = 0; ks < 2; ks++) {                                       \
            uint32_t af[4][4];                                                 \
            _Pragma("unroll")                                                  \
            for (int mt = 0; mt < 4; mt++)                                     \
                ldsm_x4(af[mt][0], af[mt][1], af[mt][2], af[mt][3],            \
                        sa + aOff + (uint32_t)(mt * 16 * ROWB)                 \
                           + (uint32_t)(ks * 32));                             \
            _Pragma("unroll")                                                  \
            for (int ntp = 0; ntp < 4; ntp++) {                                \
                uint32_t b0, b1, b2, b3;                                       \
                ldsm_x4(b0, b1, b2, b3,                                        \
                        sa + bOff + (uint32_t)(ntp * 16 * ROWB)                \
                           + (uint32_t)(ks * 32));                             \
                _Pragma("unroll")                                              \
                for (int mt = 0; mt < 4; mt++) {                               \
                    mma_f16(ACC[mt][2 * ntp],                                  \
                            af[mt][0], af[mt][1], af[mt][2], af[mt][3], b0, b1);\
                    mma_f16(ACC[mt][2 * ntp + 1],                              \
                            af[mt][0], af[mt][1], af[mt][2], af[mt][3], b2, b3);\
                }                                                              \
            }                                                                  \
        }                                                                      \
        stage = (stage + 1 == STG) ? 0 : stage + 1;                            \
    }

// ============== fused GEMM1 + attnV:  vp = v@Wv^T;  O = P @ vp ==============
// CTA (bx, by): rows by*128 (= batches 2by, 2by+1), cols bx*256 (= heads 2bx, 2bx+1).
__global__ void __launch_bounds__(256, 1) hgemm_av(
    const __half* __restrict__ A, const __half* __restrict__ W,
    const float* __restrict__ attn_src, __half* __restrict__ O)
{
    extern __shared__ __half smh[];
    const uint32_t sbase = smem_u32(smh);
    const int tid = threadIdx.x;
    const int wid = tid >> 5, lane = tid & 31;
    const int gid = lane >> 2, tg = lane & 3;
    const int wm = wid >> 2, wn = wid & 3;
    const int bm = blockIdx.y * BM;
    const int bn = blockIdx.x * BN;

    float acc[4][8][4];
    #pragma unroll
    for (int i = 0; i < 4; i++)
        #pragma unroll
        for (int j = 0; j < 8; j++)
            #pragma unroll
            for (int r = 0; r < 4; r++) acc[i][j][r] = 0.f;

    GEMM_PROLOG()

    // ---- prefetch attn (2 heads x 64 rows x 64 f32 = 32 KB) as group 0 -----
    {
        #pragma unroll
        for (int i = 0; i < 8; i++) {
            const int c = tid + 256 * i;
            const int hh = c >> 10;              // head within CTA (0/1)
            const int c2 = c & 1023;
            const int prow = c2 >> 4;            // 0..63  (pb*32+pq)
            const int off16 = c2 & 15;           // 16B chunk within row
            const int pb = prow >> 5, pq = prow & 31;
            const float* src = attn_src
                + ((((size_t)(2 * blockIdx.x + hh) * B_ + (2 * blockIdx.y + pb)) * LQ_ + pq) * LK_)
                + off16 * 4;
            cp_async16(sbase + PF_OFF + (uint32_t)(hh * 16384 + prow * 256 + off16 * 16), src);
        }
    }
    CP_COMMIT();

    load_tile(0, 0); CP_COMMIT();
    load_tile(1, 1); CP_COMMIT();

    GEMM_MAINLOOP(acc)

    asm volatile("cp.async.wait_group 0;" ::: "memory");
    __syncthreads();

    // ---- O phase: vp tile -> smem fp16 (stage memory reused) ---------------
    __half* vp_s = smh;                 // [128][VPS]
    __half* P_s  = smh + P_S_HOFF;      // [2][64][PS]

    #pragma unroll
    for (int mt = 0; mt < 4; mt++) {
        const int row = wm * 64 + mt * 16 + gid;
        #pragma unroll
        for (int nt = 0; nt < 8; nt++) {
            const int col = wn * 64 + nt * 8 + tg * 2;
            *(__half2*)(vp_s + row * VPS + col) =
                __floats2half2_rn(acc[mt][nt][0], acc[mt][nt][1]);
            *(__half2*)(vp_s + (row + 8) * VPS + col) =
                __floats2half2_rn(acc[mt][nt][2], acc[mt][nt][3]);
        }
    }

    // convert prefetched fp32 attn (smem) -> fp16 P_s
    {
        const int prow = tid >> 2;
        const int cb   = (tid & 3) * 16;
        #pragma unroll
        for (int hh = 0; hh < 2; hh++) {
            const float* srcf = (const float*)((const char*)smh + PF_OFF)
                              + hh * 4096 + prow * 64 + cb;
            __half* dstp = P_s + hh * 64 * PS + prow * PS + cb;
            #pragma unroll
            for (int j = 0; j < 4; j++) {
                float4 f = ((const float4*)srcf)[j];
                *(__half2*)(dstp + j * 4)     = __floats2half2_rn(f.x, f.y);
                *(__half2*)(dstp + j * 4 + 2) = __floats2half2_rn(f.z, f.w);
            }
        }
    }
    __syncthreads();

    // ---- O = P(32x64) @ vp(64x64) per (batch, col-quarter) ------------------
    const int wb = wid >> 2;            // batch within CTA
    const int wc = wid & 3;             // 64-col quarter of 256
    const int hq = wc >> 1;             // head of this quarter
    float oac[2][8][4];
    #pragma unroll
    for (int i = 0; i < 2; i++)
        #pragma unroll
        for (int j = 0; j < 8; j++)
            #pragma unroll
            for (int r = 0; r < 4; r++) oac[i][j][r] = 0.f;

    const uint32_t aOff2 = sbase + (uint32_t)(P_S_HOFF * 2)
        + (uint32_t)(hq * 64 + wb * 32 + (lane & 15)) * (PS * 2)
        + (uint32_t)(lane >> 4) * 16;
    const uint32_t bRow2 = (uint32_t)((lane & 7) + ((lane >> 3) & 1) * 8);
    const uint32_t bOff2 = sbase
        + (uint32_t)(wb * 64 + bRow2) * (VPS * 2)
        + (uint32_t)(wc * 64 + (lane >> 4) * 8) * 2;

    #pragma unroll
    for (int ks = 0; ks < 4; ks++) {
        uint32_t af[2][4];
        #pragma unroll
        for (int mt = 0; mt < 2; mt++)
            ldsm_x4(af[mt][0], af[mt][1], af[mt][2], af[mt][3],
                    aOff2 + (uint32_t)(mt * 16 * PS * 2) + (uint32_t)(ks * 32));
        #pragma unroll
        for (int ntp = 0; ntp < 4; ntp++) {
            uint32_t b0, b1, b2, b3;
            ldsm_x4_t(b0, b1, b2, b3,
                      bOff2 + (uint32_t)(ks * 16 * VPS * 2) + (uint32_t)(ntp * 16 * 2));
            #pragma unroll
            for (int mt = 0; mt < 2; mt++) {
                mma_f16(oac[mt][2 * ntp],     af[mt][0], af[mt][1], af[mt][2], af[mt][3], b0, b1);
                mma_f16(oac[mt][2 * ntp + 1], af[mt][0], af[mt][1], af[mt][2], af[mt][3], b2, b3);
            }
        }
    }

    {
        const size_t rb = ((size_t)(2 * blockIdx.y + wb)) * LQ_;
        #pragma unroll
        for (int mt = 0; mt < 2; mt++) {
            const int q0 = mt * 16 + gid;
            #pragma unroll
            for (int nt = 0; nt < 8; nt++) {
                const int col = blockIdx.x * BN + wc * 64 + nt * 8 + tg * 2;
                *(__half2*)(O + (rb + q0) * DM_ + col) =
                    __floats2half2_rn(oac[mt][nt][0], oac[mt][nt][1]);
                *(__half2*)(O + (rb + q0 + 8) * DM_ + col) =
                    __floats2half2_rn(oac[mt][nt][2], oac[mt][nt][3]);
            }
        }
    }
}

// ====================== plain fp16 GEMM (GEMM2) ==============================
__global__ void __launch_bounds__(256, 1) hgemm(
    const __half* __restrict__ A, const __half* __restrict__ W,
    __half* __restrict__ C)
{
    extern __shared__ __half smh[];
    const uint32_t sbase = smem_u32(smh);
    const int tid = threadIdx.x;
    const int wid = tid >> 5, lane = tid & 31;
    const int gid = lane >> 2, tg = lane & 3;
    const int wm = wid >> 2, wn = wid & 3;
    const int bm = blockIdx.y * BM;
    const int bn = blockIdx.x * BN;

    float acc[4][8][4];
    #pragma unroll
    for (int i = 0; i < 4; i++)
        #pragma unroll
        for (int j = 0; j < 8; j++)
            #pragma unroll
            for (int r = 0; r < 4; r++) acc[i][j][r] = 0.f;

    GEMM_PROLOG()

    load_tile(0, 0); CP_COMMIT();
    load_tile(1, 1); CP_COMMIT();

    GEMM_MAINLOOP(acc)

    #pragma unroll
    for (int mt = 0; mt < 4; mt++) {
        const int row0 = bm + wm * 64 + mt * 16 + gid;
        #pragma unroll
        for (int nt = 0; nt < 8; nt++) {
            const int col0 = bn + wn * 64 + nt * 8 + tg * 2;
            *(__half2*)(C + (size_t)row0 * DM_ + col0) =
                __floats2half2_rn(acc[mt][nt][0], acc[mt][nt][1]);
            *(__half2*)(C + (size_t)(row0 + 8) * DM_ + col0) =
                __floats2half2_rn(acc[mt][nt][2], acc[mt][nt][3]);
        }
    }
}

// ---------------- fp32 -> fp16 converters -----------------------------------
__global__ void conv_f2h_kernel(const float* __restrict__ src,
                                __half* __restrict__ dst, size_t n) {
    size_t i = ((size_t)blockIdx.x * blockDim.x + threadIdx.x) * 8;
    if (i >= n) return;
    float4 f0 = *(const float4*)(src + i);
    float4 f1 = *(const float4*)(src + i + 4);
    __half2 h[4];
    h[0] = __floats2half2_rn(f0.x, f0.y);
    h[1] = __floats2half2_rn(f0.z, f0.w);
    h[2] = __floats2half2_rn(f1.x, f1.y);
    h[3] = __floats2half2_rn(f1.z, f1.w);
    *(uint4*)(dst + i) = *(uint4*)h;
}

// -------- effective map weights (warp-per-output) + mask detect -------------
__global__ void weff_detect_kernel(const float* __restrict__ Wq,
                                   const float* __restrict__ Wk,
                                   const float* __restrict__ Wmap,
                                   const unsigned char* __restrict__ m) {
    if (blockIdx.x == 512) {
        __shared__ int f0, f1;
        if (threadIdx.x == 0) { f0 = 0; f1 = 0; }
        __syncthreads();
        int lf = 0, lb = 0;
        for (int i = threadIdx.x; i < 4096; i += blockDim.x) {
            unsigned char c = m[i];
            if (c == 0x3Fu || c == 0x80u) lf = 1;
            if (c != 0u && (i & 3) != 0) lb = 1;
        }
        if (lf) atomicOr(&f0, 1);
        if (lb) atomicOr(&f1, 1);
        __syncthreads();
        if (threadIdx.x == 0) g_maskmode = f0 ? 2 : (f1 ? 0 : 1);
        return;
    }
    const int tid = threadIdx.x;
    const int wid = tid >> 5, lane = tid & 31;
    const int t = blockIdx.x * 8 + wid;
    const int isK = t >= H_ * DM_;
    const int r = isK ? (t - H_ * DM_) : t;
    const int h = r / DM_, dm = r % DM_;
    const float* W  = isK ? Wk : Wq;
    const float* wm = Wmap + (isK ? DK_ : 0);
    const float* Wp = W + (size_t)(h * DK_) * DM_ + dm;
    float s = 0.f;
    #pragma unroll
    for (int d4 = 0; d4 < 4; d4++) {
        const int d = lane + d4 * 32;
        s += wm[d] * Wp[(size_t)d * DM_];
    }
    #pragma unroll
    for (int o = 16; o; o >>= 1) s += __shfl_xor_sync(0xffffffffu, s, o);
    if (lane == 0) {
        if (isK) g_wkeff[r] = s; else g_wqeff[r] = s;
    }
}

// ---------------- fused scores + softmax + attn write ----------------------
__global__ __launch_bounds__(256) void attn_kernel(
    const float* __restrict__ qin, const float* __restrict__ kin,
    const void* __restrict__ mask, float* __restrict__ attn_buf)
{
    __shared__ float wS[2 * H_ * DM_];
    __shared__ float sqS[H_ * LQ_];
    __shared__ float skS[H_ * LK_];
    const int b = blockIdx.x;
    const int tid = threadIdx.x, warp = tid >> 5, lane = tid & 31;

    for (int i = tid; i < H_ * DM_; i += 256) {
        wS[i]            = g_wqeff[i];
        wS[H_ * DM_ + i] = g_wkeff[i];
    }
    __syncthreads();

    for (int j = warp; j < LQ_ + LK_; j += 8) {
        const float* vec;
        const float* wf;
        if (j < LQ_) { vec = qin + ((size_t)b * LQ_ + j) * DM_;         wf = wS; }
        else         { vec = kin + ((size_t)b * LK_ + (j - LQ_)) * DM_; wf = wS + H_ * DM_; }
        const float4* v4 = (const float4*)vec;
        const float4* w0 = (const float4*)(wf);
        const float4* w1 = (const float4*)(wf + DM_);
        const float4* w2 = (const float4*)(wf + 2 * DM_);
        const float4* w3 = (const float4*)(wf + 3 * DM_);
        float s0 = 0.f, s1 = 0.f, s2 = 0.f, s3 = 0.f;
        #pragma unroll
        for (int it = 0; it < 4; it++) {
            const int idx = lane + it * 32;
            float4 x = v4[idx];
            float4 a0 = w0[idx];
            s0 += x.x * a0.x + x.y * a0.y + x.z * a0.z + x.w * a0.w;
            float4 a1 = w1[idx];
            s1 += x.x * a1.x + x.y * a1.y + x.z * a1.z + x.w * a1.w;
            float4 a2 = w2[idx];
            s2 += x.x * a2.x + x.y * a2.y + x.z * a2.z + x.w * a2.w;
            float4 a3 = w3[idx];
            s3 += x.x * a3.x + x.y * a3.y + x.z * a3.z + x.w * a3.w;
        }
        #pragma unroll
        for (int o = 16; o; o >>= 1) {
            s0 += __shfl_xor_sync(0xffffffffu, s0, o);
            s1 += __shfl_xor_sync(0xffffffffu, s1, o);
            s2 += __shfl_xor_sync(0xffffffffu, s2, o);
            s3 += __shfl_xor_sync(0xffffffffu, s3, o);
        }
        if (lane == 0) {
            if (j < LQ_) {
                sqS[0 * LQ_ + j] = s0; sqS[1 * LQ_ + j] = s1;
                sqS[2 * LQ_ + j] = s2; sqS[3 * LQ_ + j] = s3;
            } else {
                int kk = j - LQ_;
                skS[0 * LK_ + kk] = s0; skS[1 * LK_ + kk] = s1;
                skS[2 * LK_ + kk] = s2; skS[3 * LK_ + kk] = s3;
            }
        }
    }
    __syncthreads();

    const int mm = g_maskmode;
    for (int r = warp; r < H_ * LQ_; r += 8) {
        const int h = r >> 5, qq = r & 31;
        const float sq = sqS[r];
        const size_t mbase = ((size_t)b * LQ_ + qq) * LK_;
        bool m0 = load_mask(mask, mm, mbase + lane);
        bool m1 = load_mask(mask, mm, mbase + lane + 32);
        float v0 = m0 ? -1e10f : sq + skS[h * LK_ + lane];
        float v1 = m1 ? -1e10f : sq + skS[h * LK_ + lane + 32];
        float mx = fmaxf(v0, v1);
        #pragma unroll
        for (int o = 16; o; o >>= 1) mx = fmaxf(mx, __shfl_xor_sync(0xffffffffu, mx, o));
        float p0 = expf(v0 - mx), p1 = expf(v1 - mx);
        float sm = p0 + p1;
        #pragma unroll
        for (int o = 16; o; o >>= 1) sm += __shfl_xor_sync(0xffffffffu, sm, o);
        float inv = 1.0f / sm;
        p0 *= inv; p1 *= inv;
        const size_t ob = (((size_t)h * B_ + b) * LQ_ + qq) * LK_;
        attn_buf[ob + lane]      = p0;
        attn_buf[ob + lane + 32] = p1;
    }
}

// ---------------- bias + leakyReLU + residual + LayerNorm (vectorized) -----
__global__ __launch_bounds__(128) void epilogue_kernel(
    const float* __restrict__ qin, const float* __restrict__ fcb,
    const float* __restrict__ gamma, const float* __restrict__ beta,
    float* __restrict__ out)
{
    const int row = blockIdx.x;
    const int tid = threadIdx.x;
    const int j0  = tid * 4;
    __shared__ float rs[8];

    uint2 hraw = *(const uint2*)(g_fch + (size_t)row * DM_ + j0);
    const __half2* hp = (const __half2*)&hraw;
    float2 fa = __half22float2(hp[0]);
    float2 fb = __half22float2(hp[1]);
    float4 qv = *(const float4*)(qin + (size_t)row * DM_ + j0);
    float4 bv = *(const float4*)(fcb + j0);

    float y[4];
    float xs[4] = { fa.x + bv.x, fa.y + bv.y, fb.x + bv.z, fb.y + bv.w };
    float qf[4] = { qv.x, qv.y, qv.z, qv.w };
    float s = 0.f, s2 = 0.f;
    #pragma unroll
    for (int i = 0; i < 4; i++) {
        float x = xs[i];
        x = (x >= 0.f) ? x : 0.2f * x;
        x += qf[i];
        y[i] = x; s += x; s2 += x * x;
    }
    #pragma unroll
    for (int o = 16; o; o >>= 1) {
        s  += __shfl_xor_sync(0xffffffffu, s, o);
        s2 += __shfl_xor_sync(0xffffffffu, s2, o);
    }
    const int warp = tid >> 5, lane = tid & 31;
    if (lane == 0) { rs[warp] = s; rs[4 + warp] = s2; }
    __syncthreads();
    s  = rs[0] + rs[1] + rs[2] + rs[3];
    s2 = rs[4] + rs[5] + rs[6] + rs[7];
    const float mu  = s * (1.0f / DM_);
    const float var = s2 * (1.0f / DM_) - mu * mu;
    const float inv = rsqrtf(var + 1e-5f);

    float4 gv = *(const float4*)(gamma + j0);
    float4 bt = *(const float4*)(beta + j0);
    float4 ov;
    ov.x = gv.x * (y[0] - mu) * inv + bt.x;
    ov.y = gv.y * (y[1] - mu) * inv + bt.y;
    ov.z = gv.z * (y[2] - mu) * inv + bt.z;
    ov.w = gv.w * (y[3] - mu) * inv + bt.w;
    *(float4*)(out + (size_t)row * DM_ + j0) = ov;
}

// ---------------- launch ----------------------------------------------------
extern "C" void kernel_launch(void* const* d_in, const int* in_sizes, int n_in,
                              void* d_out, int out_size)
{
    const float* q    = (const float*)d_in[0];
    const float* k    = (const float*)d_in[1];
    const float* v    = (const float*)d_in[2];
    const void*  mask =               d_in[3];
    const float* Wq   = (const float*)d_in[4];
    const float* Wk   = (const float*)d_in[5];
    const float* Wv   = (const float*)d_in[6];
    const float* Wmap = (const float*)d_in[7];
    const float* fcW  = (const float*)d_in[8];
    const float* fcb  = (const float*)d_in[9];
    const float* gma  = (const float*)d_in[10];
    const float* bta  = (const float*)d_in[11];
    float* out = (float*)d_out;

    const size_t out_elems  = (size_t)B_ * LQ_ * DM_;
    const size_t attn_elems = (size_t)H_ * B_ * LQ_ * LK_;
    int write_attn = ((size_t)out_size >= out_elems + attn_elems) ? 1 : 0;

    void *p_vh = nullptr, *p_wvh = nullptr, *p_fcwh = nullptr;
    void *p_oh = nullptr, *p_fch = nullptr, *p_attn = nullptr;
    cudaGetSymbolAddress(&p_vh, g_vh);
    cudaGetSymbolAddress(&p_wvh, g_wvh);
    cudaGetSymbolAddress(&p_fcwh, g_fcwh);
    cudaGetSymbolAddress(&p_oh, g_oh);
    cudaGetSymbolAddress(&p_fch, g_fch);
    cudaGetSymbolAddress(&p_attn, g_attn);

    float* attn_buf = write_attn ? (out + out_elems) : (float*)p_attn;

    cudaFuncSetAttribute(hgemm_av, cudaFuncAttributeMaxDynamicSharedMemorySize, AV_SMEM);
    cudaFuncSetAttribute(hgemm, cudaFuncAttributeMaxDynamicSharedMemorySize, GEMM_SMEM);

    static cudaStream_t s1 = nullptr;
    static cudaEvent_t evFork = nullptr, evJoin = nullptr;
    if (s1 == nullptr) {
        cudaStreamCreateWithFlags(&s1, cudaStreamNonBlocking);
        cudaEventCreateWithFlags(&evFork, cudaEventDisableTiming);
        cudaEventCreateWithFlags(&evJoin, cudaEventDisableTiming);
    }

    cudaEventRecord(evFork, 0);
    cudaStreamWaitEvent(s1, evFork, 0);
    {
        size_t nv = (size_t)B_ * LK_ * DM_;
        conv_f2h_kernel<<<(unsigned)(nv / (256 * 8)), 256, 0, s1>>>(v, (__half*)p_vh, nv);
        size_t nw = (size_t)DM_ * DM_;
        conv_f2h_kernel<<<(unsigned)(nw / (256 * 8)), 256, 0, s1>>>(Wv, (__half*)p_wvh, nw);
        conv_f2h_kernel<<<(unsigned)(nw / (256 * 8)), 256, 0, s1>>>(fcW, (__half*)p_fcwh, nw);
    }
    cudaEventRecord(evJoin, s1);

    weff_detect_kernel<<<513, 256>>>(Wq, Wk, Wmap, (const unsigned char*)mask);
    attn_kernel<<<B_, 256>>>(q, k, mask, attn_buf);

    cudaStreamWaitEvent(0, evJoin, 0);

    // fused: vp = v@Wv^T (per-tile) then O = attn @ vp  -> g_oh (fp16)
    {
        dim3 grid(DM_ / BN, (B_ * LK_) / BM);   // (2, 512)
        hgemm_av<<<grid, 256, AV_SMEM>>>((const __half*)p_vh, (const __half*)p_wvh,
                                         attn_buf, (__half*)p_oh);
    }

    // fc = oattn @ fcW^T -> g_fch (fp16)
    {
        dim3 grid(DM_ / BN, (B_ * LQ_) / BM);   // (2, 256)
        hgemm<<<grid, 256, GEMM_SMEM>>>((const __half*)p_oh, (const __half*)p_fcwh,
                                        (__half*)p_fch);
    }

    epilogue_kernel<<<B_ * LQ_, 128>>>(q, fcb, gma, bta, out);
}

// round 14
// speedup vs baseline: 1.0147x; 1.0147x over previous
#include <cuda_runtime.h>
#include <cuda_fp16.h>
#include <cstdint>
#include <cstddef>

// Problem constants
#define H_    4
#define DM_   512
#define DK_   128
#define B_    1024
#define LQ_   32
#define LK_   64

// ---------------- scratch (device globals; no allocation allowed) ----------
__device__ float g_wqeff[H_ * DM_];
__device__ float g_wkeff[H_ * DM_];
__device__ float g_attn[(size_t)H_ * B_ * LQ_ * LK_];            //  33 MB (fallback)
__device__ __align__(16) __half g_vh[(size_t)B_ * LK_ * DM_];    //  67 MB (v fp16)
__device__ __align__(16) __half g_wvh[DM_ * DM_];                // 0.5 MB
__device__ __align__(16) __half g_fcwh[DM_ * DM_];               // 0.5 MB
__device__ __align__(16) __half g_oh[(size_t)B_ * LQ_ * DM_];    //  33 MB (oattn fp16)
__device__ __align__(16) __half g_fch[(size_t)B_ * LQ_ * DM_];   //  33 MB (fc staging fp16)
__device__ int   g_maskmode;
__device__ unsigned int g_cnt[256];                              // GEMM2 row-group arrivals

__device__ __forceinline__ uint32_t smem_u32(const void* p) {
    uint32_t a;
    asm("{ .reg .u64 t; cvta.to.shared.u64 t, %1; cvt.u32.u64 %0, t; }"
        : "=r"(a) : "l"(p));
    return a;
}
__device__ __forceinline__ void cp_async16(uint32_t dst, const void* src) {
    asm volatile("cp.async.cg.shared.global [%0], [%1], 16;" :: "r"(dst), "l"(src));
}
#define CP_COMMIT() asm volatile("cp.async.commit_group;" ::: "memory")
#define CP_WAIT1()  asm volatile("cp.async.wait_group 1;" ::: "memory")

__device__ __forceinline__ void ldsm_x4(uint32_t& r0, uint32_t& r1, uint32_t& r2,
                                        uint32_t& r3, uint32_t addr) {
    asm volatile("ldmatrix.sync.aligned.m8n8.x4.shared.b16 {%0,%1,%2,%3}, [%4];"
                 : "=r"(r0), "=r"(r1), "=r"(r2), "=r"(r3) : "r"(addr));
}
__device__ __forceinline__ void ldsm_x4_t(uint32_t& r0, uint32_t& r1, uint32_t& r2,
                                          uint32_t& r3, uint32_t addr) {
    asm volatile("ldmatrix.sync.aligned.m8n8.x4.trans.shared.b16 {%0,%1,%2,%3}, [%4];"
                 : "=r"(r0), "=r"(r1), "=r"(r2), "=r"(r3) : "r"(addr));
}
__device__ __forceinline__ void mma_f16(float* c,
                                        uint32_t a0, uint32_t a1, uint32_t a2, uint32_t a3,
                                        uint32_t b0, uint32_t b1) {
    asm volatile("mma.sync.aligned.m16n8k16.row.col.f32.f16.f16.f32 "
                 "{%0,%1,%2,%3}, {%4,%5,%6,%7}, {%8,%9}, {%0,%1,%2,%3};"
                 : "+f"(c[0]), "+f"(c[1]), "+f"(c[2]), "+f"(c[3])
                 : "r"(a0), "r"(a1), "r"(a2), "r"(a3), "r"(b0), "r"(b1));
}

__device__ __forceinline__ bool load_mask(const void* m, int mode, size_t idx) {
    if (mode == 2) return ((const float*)m)[idx] != 0.0f;
    if (mode == 1) return ((const int*)m)[idx] != 0;
    return ((const unsigned char*)m)[idx] != 0u;
}

// ====================== GEMM tiling constants ===============================
// 256 threads = 8 warps (2m x 4n), warp tile 64x32. 2 CTAs/SM -> 16 warps/SM.
#define BM 128
#define BN 128
#define BK 32
#define NKT (DM_ / BK)        // 16
#define STG 3
#define SROWH 40              // halfs per smem row (80 bytes)
#define STG_BYTES (2 * BM * SROWH * 2)      // A+B per stage = 20480 B
#define GEMM_SMEM (STG * STG_BYTES)         // 61440 B
// O-phase smem layout (reuses stage memory after mainloop)
#define VPS 136               // vp_s stride in halfs
#define PS  72                // P_s stride in halfs
#define P_S_OFF (128 * VPS)   // halfs offset of P_s
// fp32 attn prefetch region (beyond pipeline stages; persistent)
#define PF_OFF  GEMM_SMEM                   // bytes; [64][64] f32 = 16384 B
#define AV_SMEM (GEMM_SMEM + 16384)         // 77824 B

// ---- shared mainloop (macro) -----------------------------------------------
#define GEMM_CORE(ACC)                                                          \
    const __half* ga0 = A + (size_t)(bm + lrow) * DM_ + lch;                    \
    const __half* gb0 = W + (size_t)(bn + lrow) * DM_ + lch;                    \
    auto load_tile = [&](int kt, int s) {                                       \
        uint32_t da = sbase + (uint32_t)(s * STG_BYTES)                         \
                    + (uint32_t)lrow * (SROWH * 2) + (uint32_t)lch * 2;         \
        uint32_t db = da + BM * SROWH * 2;                                      \
        const __half* ga = ga0 + kt * BK;                                       \
        const __half* gb = gb0 + kt * BK;                                       \
        cp_async16(da,      ga);                                                \
        cp_async16(da + 16, ga + 8);                                            \
        cp_async16(db,      gb);                                                \
        cp_async16(db + 16, gb + 8);                                            \
    };                                                                          \
    const uint32_t aOff = (uint32_t)(wm * 64 + (lane & 15)) * (SROWH * 2)       \
                        + (uint32_t)(lane >> 4) * 16;                           \
    const uint32_t bOff = (uint32_t)(BM * SROWH * 2)                            \
        + (uint32_t)(wn * 32 + (lane & 7) + ((lane >> 4) << 3)) * (SROWH * 2)   \
        + (uint32_t)((lane >> 3) & 1) * 16;

#define GEMM_MAINLOOP(ACC)                                                      \
    int stage = 0;                                                              \
    for (int kt = 0; kt < NKT; kt++) {                                          \
        CP_WAIT1();                                                             \
        __syncthreads();                                                        \
        if (kt + 2 < NKT) load_tile(kt + 2, (kt + 2) % STG);                    \
        CP_COMMIT();                                                            \
        const uint32_t sa = sbase + (uint32_t)(stage * STG_BYTES);              \
        _Pragma("unroll")                                                       \
        for (int ks = 0; ks < 2; ks++) {                                        \
            uint32_t af[4][4];                                                  \
            _Pragma("unroll")                                                   \
            for (int mt = 0; mt < 4; mt++)                                      \
                ldsm_x4(af[mt][0], af[mt][1], af[mt][2], af[mt][3],             \
                        sa + aOff + (uint32_t)(mt * 16 * SROWH * 2)             \
                           + (uint32_t)(ks * 32));                              \
            _Pragma("unroll")                                                   \
            for (int ntp = 0; ntp < 2; ntp++) {                                 \
                uint32_t b0, b1, b2, b3;                                        \
                ldsm_x4(b0, b1, b2, b3,                                         \
                        sa + bOff + (uint32_t)(ntp * 16 * SROWH * 2)            \
                           + (uint32_t)(ks * 32));                              \
                _Pragma("unroll")                                               \
                for (int mt = 0; mt < 4; mt++) {                                \
                    mma_f16(ACC[mt][2 * ntp],                                   \
                            af[mt][0], af[mt][1], af[mt][2], af[mt][3], b0, b1);\
                    mma_f16(ACC[mt][2 * ntp + 1],                               \
                            af[mt][0], af[mt][1], af[mt][2], af[mt][3], b2, b3);\
                }                                                               \
            }                                                                   \
        }                                                                       \
        stage = (stage + 1 == STG) ? 0 : stage + 1;                             \
    }

// ============== fused GEMM1 + attnV:  vp = v@Wv^T;  O = P @ vp ==============
__global__ void __launch_bounds__(256, 2) hgemm_av(
    const __half* __restrict__ A, const __half* __restrict__ W,
    const float* __restrict__ attn_src, __half* __restrict__ O)
{
    extern __shared__ __half smh[];
    const uint32_t sbase = smem_u32(smh);
    const int tid = threadIdx.x;
    const int wid = tid >> 5, lane = tid & 31;
    const int gid = lane >> 2, tg = lane & 3;
    const int wm = wid >> 2, wn = wid & 3;
    const int bm = blockIdx.y * BM;
    const int bn = blockIdx.x * BN;
    const int lrow = tid >> 1;
    const int lch  = (tid & 1) * 16;

    float acc[4][4][4];
    #pragma unroll
    for (int i = 0; i < 4; i++)
        #pragma unroll
        for (int j = 0; j < 4; j++)
            #pragma unroll
            for (int r = 0; r < 4; r++) acc[i][j][r] = 0.f;

    GEMM_CORE(acc)

    // ---- prefetch attn tile (fp32, 16 KB) as cp.async group 0 --------------
    {
        const int prow = tid >> 2;
        const int pb   = prow >> 5;
        const int pq   = prow & 31;
        const int cb   = (tid & 3) * 16;
        const float* src = attn_src
            + ((((size_t)blockIdx.x * B_ + (2 * blockIdx.y + pb)) * LQ_ + pq) * LK_) + cb;
        uint32_t dst = sbase + PF_OFF + (uint32_t)(prow * 64 + cb) * 4;
        cp_async16(dst,      src);
        cp_async16(dst + 16, src + 4);
        cp_async16(dst + 32, src + 8);
        cp_async16(dst + 48, src + 12);
    }
    CP_COMMIT();

    load_tile(0, 0); CP_COMMIT();
    load_tile(1, 1); CP_COMMIT();

    GEMM_MAINLOOP(acc)

    asm volatile("cp.async.wait_group 0;" ::: "memory");
    __syncthreads();

    // ---- O phase: vp tile -> smem fp16; P from prefetched smem -> fp16 ------
    __half* vp_s = smh;
    __half* P_s  = smh + P_S_OFF;

    #pragma unroll
    for (int mt = 0; mt < 4; mt++) {
        const int row = wm * 64 + mt * 16 + gid;
        #pragma unroll
        for (int nt = 0; nt < 4; nt++) {
            const int col = wn * 32 + nt * 8 + tg * 2;
            *(__half2*)(vp_s + row * VPS + col) =
                __floats2half2_rn(acc[mt][nt][0], acc[mt][nt][1]);
            *(__half2*)(vp_s + (row + 8) * VPS + col) =
                __floats2half2_rn(acc[mt][nt][2], acc[mt][nt][3]);
        }
    }

    {
        const int prow = tid >> 2;
        const int cb   = (tid & 3) * 16;
        const float* srcf = (const float*)((const char*)smh + PF_OFF) + prow * 64 + cb;
        #pragma unroll
        for (int j = 0; j < 4; j++) {
            float4 f = ((const float4*)srcf)[j];
            *(__half2*)(P_s + prow * PS + cb + j * 4)     = __floats2half2_rn(f.x, f.y);
            *(__half2*)(P_s + prow * PS + cb + j * 4 + 2) = __floats2half2_rn(f.z, f.w);
        }
    }
    __syncthreads();

    const int wb = wid >> 2;
    const int wc = wid & 3;
    float oac[2][4][4];
    #pragma unroll
    for (int i = 0; i < 2; i++)
        #pragma unroll
        for (int j = 0; j < 4; j++)
            #pragma unroll
            for (int r = 0; r < 4; r++) oac[i][j][r] = 0.f;

    const uint32_t pbase  = sbase + (uint32_t)(P_S_OFF * 2);
    const uint32_t aOff2  = pbase
        + (uint32_t)(wb * 32 + (lane & 15)) * (PS * 2) + (uint32_t)(lane >> 4) * 16;
    const uint32_t bRow2  = (uint32_t)((lane & 7) + ((lane >> 3) & 1) * 8);
    const uint32_t bOff2  = sbase
        + (uint32_t)(wb * 64 + bRow2) * (VPS * 2)
        + (uint32_t)(wc * 32 + (lane >> 4) * 8) * 2;

    #pragma unroll
    for (int ks = 0; ks < 4; ks++) {
        uint32_t af[2][4];
        #pragma unroll
        for (int mt = 0; mt < 2; mt++)
            ldsm_x4(af[mt][0], af[mt][1], af[mt][2], af[mt][3],
                    aOff2 + (uint32_t)(mt * 16 * PS * 2) + (uint32_t)(ks * 32));
        #pragma unroll
        for (int ntp = 0; ntp < 2; ntp++) {
            uint32_t b0, b1, b2, b3;
            ldsm_x4_t(b0, b1, b2, b3,
                      bOff2 + (uint32_t)(ks * 16 * VPS * 2) + (uint32_t)(ntp * 16 * 2));
            #pragma unroll
            for (int mt = 0; mt < 2; mt++) {
                mma_f16(oac[mt][2 * ntp],     af[mt][0], af[mt][1], af[mt][2], af[mt][3], b0, b1);
                mma_f16(oac[mt][2 * ntp + 1], af[mt][0], af[mt][1], af[mt][2], af[mt][3], b2, b3);
            }
        }
    }

    {
        const size_t rb = ((size_t)(2 * blockIdx.y + wb)) * LQ_;
        #pragma unroll
        for (int mt = 0; mt < 2; mt++) {
            const int q0 = mt * 16 + gid;
            #pragma unroll
            for (int nt = 0; nt < 4; nt++) {
                const int col = blockIdx.x * BN + wc * 32 + nt * 8 + tg * 2;
                *(__half2*)(O + (rb + q0) * DM_ + col) =
                    __floats2half2_rn(oac[mt][nt][0], oac[mt][nt][1]);
                *(__half2*)(O + (rb + q0 + 8) * DM_ + col) =
                    __floats2half2_rn(oac[mt][nt][2], oac[mt][nt][3]);
            }
        }
    }
}

// ====== GEMM2 + fused LayerNorm epilogue (last CTA of each row group) =======
__global__ void __launch_bounds__(256, 2) hgemm_ep(
    const __half* __restrict__ A, const __half* __restrict__ W,
    __half* __restrict__ C,
    const float* __restrict__ qin, const float* __restrict__ fcb,
    const float* __restrict__ gamma, const float* __restrict__ beta,
    float* __restrict__ out)
{
    extern __shared__ __half smh[];
    const uint32_t sbase = smem_u32(smh);
    const int tid = threadIdx.x;
    const int wid = tid >> 5, lane = tid & 31;
    const int gid = lane >> 2, tg = lane & 3;
    const int wm = wid >> 2, wn = wid & 3;
    const int bm = blockIdx.y * BM;
    const int bn = blockIdx.x * BN;
    const int lrow = tid >> 1;
    const int lch  = (tid & 1) * 16;

    float acc[4][4][4];
    #pragma unroll
    for (int i = 0; i < 4; i++)
        #pragma unroll
        for (int j = 0; j < 4; j++)
            #pragma unroll
            for (int r = 0; r < 4; r++) acc[i][j][r] = 0.f;

    GEMM_CORE(acc)

    load_tile(0, 0); CP_COMMIT();
    load_tile(1, 1); CP_COMMIT();

    GEMM_MAINLOOP(acc)

    // store staging tile (fp16)
    #pragma unroll
    for (int mt = 0; mt < 4; mt++) {
        const int row0 = bm + wm * 64 + mt * 16 + gid;
        #pragma unroll
        for (int nt = 0; nt < 4; nt++) {
            const int col0 = bn + wn * 32 + nt * 8 + tg * 2;
            *(__half2*)(C + (size_t)row0 * DM_ + col0) =
                __floats2half2_rn(acc[mt][nt][0], acc[mt][nt][1]);
            *(__half2*)(C + (size_t)(row0 + 8) * DM_ + col0) =
                __floats2half2_rn(acc[mt][nt][2], acc[mt][nt][3]);
        }
    }

    // arrival: last CTA of this 128-row group runs the LayerNorm epilogue
    __shared__ unsigned int s_last;
    __threadfence();
    __syncthreads();
    if (tid == 0) s_last = atomicAdd(&g_cnt[blockIdx.y], 1u);
    __syncthreads();
    if (s_last != 3u) return;

    // epilogue: rows [bm, bm+128), all 512 cols. warp handles 16 rows; lane
    // owns 16 fixed cols (lane*16 .. +15).
    const int c0 = lane * 16;
    float bv[16], gv[16], btv[16];
    #pragma unroll
    for (int j = 0; j < 16; j += 4) {
        float4 t;
        t = *(const float4*)(fcb + c0 + j);   bv[j] = t.x;  bv[j+1] = t.y;  bv[j+2] = t.z;  bv[j+3] = t.w;
        t = *(const float4*)(gamma + c0 + j); gv[j] = t.x;  gv[j+1] = t.y;  gv[j+2] = t.z;  gv[j+3] = t.w;
        t = *(const float4*)(beta + c0 + j);  btv[j] = t.x; btv[j+1] = t.y; btv[j+2] = t.z; btv[j+3] = t.w;
    }
    for (int rr = 0; rr < 16; rr++) {
        const int row = bm + wid * 16 + rr;
        const __half* fp = C + (size_t)row * DM_ + c0;
        const float*  qp = qin + (size_t)row * DM_ + c0;
        float y[16];
        float s = 0.f, s2 = 0.f;
        #pragma unroll
        for (int j = 0; j < 16; j += 8) {
            uint4 hraw = *(const uint4*)(fp + j);
            const __half2* hp = (const __half2*)&hraw;
            float4 qa = *(const float4*)(qp + j);
            float4 qb = *(const float4*)(qp + j + 4);
            float qf[8] = { qa.x, qa.y, qa.z, qa.w, qb.x, qb.y, qb.z, qb.w };
            #pragma unroll
            for (int u = 0; u < 4; u++) {
                float2 f = __half22float2(hp[u]);
                float x0 = f.x + bv[j + 2*u];
                float x1 = f.y + bv[j + 2*u + 1];
                x0 = (x0 >= 0.f) ? x0 : 0.2f * x0;
                x1 = (x1 >= 0.f) ? x1 : 0.2f * x1;
                x0 += qf[2*u]; x1 += qf[2*u + 1];
                y[j + 2*u] = x0; y[j + 2*u + 1] = x1;
                s += x0 + x1; s2 += x0 * x0 + x1 * x1;
            }
        }
        #pragma unroll
        for (int o = 16; o; o >>= 1) {
            s  += __shfl_xor_sync(0xffffffffu, s, o);
            s2 += __shfl_xor_sync(0xffffffffu, s2, o);
        }
        const float mu  = s * (1.0f / DM_);
        const float var = s2 * (1.0f / DM_) - mu * mu;
        const float inv = rsqrtf(var + 1e-5f);
        float* op = out + (size_t)row * DM_ + c0;
        #pragma unroll
        for (int j = 0; j < 16; j += 4) {
            float4 ov;
            ov.x = gv[j]     * (y[j]     - mu) * inv + btv[j];
            ov.y = gv[j + 1] * (y[j + 1] - mu) * inv + btv[j + 1];
            ov.z = gv[j + 2] * (y[j + 2] - mu) * inv + btv[j + 2];
            ov.w = gv[j + 3] * (y[j + 3] - mu) * inv + btv[j + 3];
            *(float4*)(op + j) = ov;
        }
    }
}

// ---------------- fp32 -> fp16 converters -----------------------------------
__global__ void conv_f2h_kernel(const float* __restrict__ src,
                                __half* __restrict__ dst, size_t n) {
    size_t i = ((size_t)blockIdx.x * blockDim.x + threadIdx.x) * 8;
    if (i >= n) return;
    float4 f0 = *(const float4*)(src + i);
    float4 f1 = *(const float4*)(src + i + 4);
    __half2 h[4];
    h[0] = __floats2half2_rn(f0.x, f0.y);
    h[1] = __floats2half2_rn(f0.z, f0.w);
    h[2] = __floats2half2_rn(f1.x, f1.y);
    h[3] = __floats2half2_rn(f1.z, f1.w);
    *(uint4*)(dst + i) = *(uint4*)h;
}

// -------- effective map weights (warp-per-output) + detect + cnt reset ------
__global__ void weff_detect_kernel(const float* __restrict__ Wq,
                                   const float* __restrict__ Wk,
                                   const float* __restrict__ Wmap,
                                   const unsigned char* __restrict__ m) {
    if (blockIdx.x == 512) {
        if (threadIdx.x < 256) g_cnt[threadIdx.x] = 0u;   // reset GEMM2 counters
        __shared__ int f0, f1;
        if (threadIdx.x == 0) { f0 = 0; f1 = 0; }
        __syncthreads();
        int lf = 0, lb = 0;
        for (int i = threadIdx.x; i < 4096; i += blockDim.x) {
            unsigned char c = m[i];
            if (c == 0x3Fu || c == 0x80u) lf = 1;
            if (c != 0u && (i & 3) != 0) lb = 1;
        }
        if (lf) atomicOr(&f0, 1);
        if (lb) atomicOr(&f1, 1);
        __syncthreads();
        if (threadIdx.x == 0) g_maskmode = f0 ? 2 : (f1 ? 0 : 1);
        return;
    }
    const int tid = threadIdx.x;
    const int wid = tid >> 5, lane = tid & 31;
    const int t = blockIdx.x * 8 + wid;
    const int isK = t >= H_ * DM_;
    const int r = isK ? (t - H_ * DM_) : t;
    const int h = r / DM_, dm = r % DM_;
    const float* W  = isK ? Wk : Wq;
    const float* wm = Wmap + (isK ? DK_ : 0);
    const float* Wp = W + (size_t)(h * DK_) * DM_ + dm;
    float s = 0.f;
    #pragma unroll
    for (int d4 = 0; d4 < 4; d4++) {
        const int d = lane + d4 * 32;
        s += wm[d] * Wp[(size_t)d * DM_];
    }
    #pragma unroll
    for (int o = 16; o; o >>= 1) s += __shfl_xor_sync(0xffffffffu, s, o);
    if (lane == 0) {
        if (isK) g_wkeff[r] = s; else g_wqeff[r] = s;
    }
}

// ---------------- fused scores + softmax + attn write ----------------------
__global__ __launch_bounds__(256) void attn_kernel(
    const float* __restrict__ qin, const float* __restrict__ kin,
    const void* __restrict__ mask, float* __restrict__ attn_buf)
{
    __shared__ float wS[2 * H_ * DM_];
    __shared__ float sqS[H_ * LQ_];
    __shared__ float skS[H_ * LK_];
    const int b = blockIdx.x;
    const int tid = threadIdx.x, warp = tid >> 5, lane = tid & 31;

    for (int i = tid; i < H_ * DM_; i += 256) {
        wS[i]            = g_wqeff[i];
        wS[H_ * DM_ + i] = g_wkeff[i];
    }
    __syncthreads();

    for (int j = warp; j < LQ_ + LK_; j += 8) {
        const float* vec;
        const float* wf;
        if (j < LQ_) { vec = qin + ((size_t)b * LQ_ + j) * DM_;         wf = wS; }
        else         { vec = kin + ((size_t)b * LK_ + (j - LQ_)) * DM_; wf = wS + H_ * DM_; }
        const float4* v4 = (const float4*)vec;
        const float4* w0 = (const float4*)(wf);
        const float4* w1 = (const float4*)(wf + DM_);
        const float4* w2 = (const float4*)(wf + 2 * DM_);
        const float4* w3 = (const float4*)(wf + 3 * DM_);
        float s0 = 0.f, s1 = 0.f, s2 = 0.f, s3 = 0.f;
        #pragma unroll
        for (int it = 0; it < 4; it++) {
            const int idx = lane + it * 32;
            float4 x = v4[idx];
            float4 a0 = w0[idx];
            s0 += x.x * a0.x + x.y * a0.y + x.z * a0.z + x.w * a0.w;
            float4 a1 = w1[idx];
            s1 += x.x * a1.x + x.y * a1.y + x.z * a1.z + x.w * a1.w;
            float4 a2 = w2[idx];
            s2 += x.x * a2.x + x.y * a2.y + x.z * a2.z + x.w * a2.w;
            float4 a3 = w3[idx];
            s3 += x.x * a3.x + x.y * a3.y + x.z * a3.z + x.w * a3.w;
        }
        #pragma unroll
        for (int o = 16; o; o >>= 1) {
            s0 += __shfl_xor_sync(0xffffffffu, s0, o);
            s1 += __shfl_xor_sync(0xffffffffu, s1, o);
            s2 += __shfl_xor_sync(0xffffffffu, s2, o);
            s3 += __shfl_xor_sync(0xffffffffu, s3, o);
        }
        if (lane == 0) {
            if (j < LQ_) {
                sqS[0 * LQ_ + j] = s0; sqS[1 * LQ_ + j] = s1;
                sqS[2 * LQ_ + j] = s2; sqS[3 * LQ_ + j] = s3;
            } else {
                int kk = j - LQ_;
                skS[0 * LK_ + kk] = s0; skS[1 * LK_ + kk] = s1;
                skS[2 * LK_ + kk] = s2; skS[3 * LK_ + kk] = s3;
            }
        }
    }
    __syncthreads();

    const int mm = g_maskmode;
    for (int r = warp; r < H_ * LQ_; r += 8) {
        const int h = r >> 5, qq = r & 31;
        const float sq = sqS[r];
        const size_t mbase = ((size_t)b * LQ_ + qq) * LK_;
        bool m0 = load_mask(mask, mm, mbase + lane);
        bool m1 = load_mask(mask, mm, mbase + lane + 32);
        float v0 = m0 ? -1e10f : sq + skS[h * LK_ + lane];
        float v1 = m1 ? -1e10f : sq + skS[h * LK_ + lane + 32];
        float mx = fmaxf(v0, v1);
        #pragma unroll
        for (int o = 16; o; o >>= 1) mx = fmaxf(mx, __shfl_xor_sync(0xffffffffu, mx, o));
        float p0 = expf(v0 - mx), p1 = expf(v1 - mx);
        float sm = p0 + p1;
        #pragma unroll
        for (int o = 16; o; o >>= 1) sm += __shfl_xor_sync(0xffffffffu, sm, o);
        float inv = 1.0f / sm;
        p0 *= inv; p1 *= inv;
        const size_t ob = (((size_t)h * B_ + b) * LQ_ + qq) * LK_;
        attn_buf[ob + lane]      = p0;
        attn_buf[ob + lane + 32] = p1;
    }
}

// ---------------- launch ----------------------------------------------------
extern "C" void kernel_launch(void* const* d_in, const int* in_sizes, int n_in,
                              void* d_out, int out_size)
{
    const float* q    = (const float*)d_in[0];
    const float* k    = (const float*)d_in[1];
    const float* v    = (const float*)d_in[2];
    const void*  mask =               d_in[3];
    const float* Wq   = (const float*)d_in[4];
    const float* Wk   = (const float*)d_in[5];
    const float* Wv   = (const float*)d_in[6];
    const float* Wmap = (const float*)d_in[7];
    const float* fcW  = (const float*)d_in[8];
    const float* fcb  = (const float*)d_in[9];
    const float* gma  = (const float*)d_in[10];
    const float* bta  = (const float*)d_in[11];
    float* out = (float*)d_out;

    const size_t out_elems  = (size_t)B_ * LQ_ * DM_;
    const size_t attn_elems = (size_t)H_ * B_ * LQ_ * LK_;
    int write_attn = ((size_t)out_size >= out_elems + attn_elems) ? 1 : 0;

    void *p_vh = nullptr, *p_wvh = nullptr, *p_fcwh = nullptr;
    void *p_oh = nullptr, *p_fch = nullptr, *p_attn = nullptr;
    cudaGetSymbolAddress(&p_vh, g_vh);
    cudaGetSymbolAddress(&p_wvh, g_wvh);
    cudaGetSymbolAddress(&p_fcwh, g_fcwh);
    cudaGetSymbolAddress(&p_oh, g_oh);
    cudaGetSymbolAddress(&p_fch, g_fch);
    cudaGetSymbolAddress(&p_attn, g_attn);

    float* attn_buf = write_attn ? (out + out_elems) : (float*)p_attn;

    cudaFuncSetAttribute(hgemm_av, cudaFuncAttributeMaxDynamicSharedMemorySize, AV_SMEM);
    cudaFuncSetAttribute(hgemm_ep, cudaFuncAttributeMaxDynamicSharedMemorySize, GEMM_SMEM);

    static cudaStream_t s1 = nullptr;
    static cudaEvent_t evFork = nullptr, evJoin = nullptr;
    if (s1 == nullptr) {
        cudaStreamCreateWithFlags(&s1, cudaStreamNonBlocking);
        cudaEventCreateWithFlags(&evFork, cudaEventDisableTiming);
        cudaEventCreateWithFlags(&evJoin, cudaEventDisableTiming);
    }

    cudaEventRecord(evFork, 0);
    cudaStreamWaitEvent(s1, evFork, 0);
    {
        size_t nv = (size_t)B_ * LK_ * DM_;
        conv_f2h_kernel<<<(unsigned)(nv / (256 * 8)), 256, 0, s1>>>(v, (__half*)p_vh, nv);
        size_t nw = (size_t)DM_ * DM_;
        conv_f2h_kernel<<<(unsigned)(nw / (256 * 8)), 256, 0, s1>>>(Wv, (__half*)p_wvh, nw);
        conv_f2h_kernel<<<(unsigned)(nw / (256 * 8)), 256, 0, s1>>>(fcW, (__half*)p_fcwh, nw);
    }
    cudaEventRecord(evJoin, s1);

    weff_detect_kernel<<<513, 256>>>(Wq, Wk, Wmap, (const unsigned char*)mask);
    attn_kernel<<<B_, 256>>>(q, k, mask, attn_buf);

    cudaStreamWaitEvent(0, evJoin, 0);

    // fused: vp = v@Wv^T (per-tile) then O = attn @ vp  -> g_oh (fp16)
    {
        dim3 grid(DM_ / BN, (B_ * LK_) / BM);   // (4, 512)
        hgemm_av<<<grid, 256, AV_SMEM>>>((const __half*)p_vh, (const __half*)p_wvh,
                                         attn_buf, (__half*)p_oh);
    }

    // fc = oattn @ fcW^T, with fused bias/leakyReLU/residual/LayerNorm -> out
    {
        dim3 grid(DM_ / BN, (B_ * LQ_) / BM);   // (4, 256)
        hgemm_ep<<<grid, 256, GEMM_SMEM>>>((const __half*)p_oh, (const __half*)p_fcwh,
                                           (__half*)p_fch, q, fcb, gma, bta, out);
    }
}

// round 15
// speedup vs baseline: 1.0817x; 1.0661x over previous
#include <cuda_runtime.h>
#include <cuda_fp16.h>
#include <cstdint>
#include <cstddef>

// Problem constants
#define H_    4
#define DM_   512
#define DK_   128
#define B_    1024
#define LQ_   32
#define LK_   64

// ---------------- scratch (device globals; no allocation allowed) ----------
__device__ float g_wqeff[H_ * DM_];
__device__ float g_wkeff[H_ * DM_];
__device__ float g_attn[(size_t)H_ * B_ * LQ_ * LK_];            //  33 MB (fallback)
__device__ __align__(16) __half g_vh[(size_t)B_ * LK_ * DM_];    //  67 MB (v fp16)
__device__ __align__(16) __half g_wvh[DM_ * DM_];                // 0.5 MB
__device__ __align__(16) __half g_fcwh[DM_ * DM_];               // 0.5 MB
__device__ __align__(16) __half g_oh[(size_t)B_ * LQ_ * DM_];    //  33 MB (oattn fp16)
__device__ __align__(16) __half g_fch[(size_t)B_ * LQ_ * DM_];   //  33 MB (fc out fp16)
__device__ int   g_maskmode;

__device__ __forceinline__ uint32_t smem_u32(const void* p) {
    uint32_t a;
    asm("{ .reg .u64 t; cvta.to.shared.u64 t, %1; cvt.u32.u64 %0, t; }"
        : "=r"(a) : "l"(p));
    return a;
}
__device__ __forceinline__ void cp_async16(uint32_t dst, const void* src) {
    asm volatile("cp.async.cg.shared.global [%0], [%1], 16;" :: "r"(dst), "l"(src));
}
#define CP_COMMIT() asm volatile("cp.async.commit_group;" ::: "memory")
#define CP_WAIT1()  asm volatile("cp.async.wait_group 1;" ::: "memory")

__device__ __forceinline__ void ldsm_x4(uint32_t& r0, uint32_t& r1, uint32_t& r2,
                                        uint32_t& r3, uint32_t addr) {
    asm volatile("ldmatrix.sync.aligned.m8n8.x4.shared.b16 {%0,%1,%2,%3}, [%4];"
                 : "=r"(r0), "=r"(r1), "=r"(r2), "=r"(r3) : "r"(addr));
}
__device__ __forceinline__ void ldsm_x4_t(uint32_t& r0, uint32_t& r1, uint32_t& r2,
                                          uint32_t& r3, uint32_t addr) {
    asm volatile("ldmatrix.sync.aligned.m8n8.x4.trans.shared.b16 {%0,%1,%2,%3}, [%4];"
                 : "=r"(r0), "=r"(r1), "=r"(r2), "=r"(r3) : "r"(addr));
}
__device__ __forceinline__ void mma_f16(float* c,
                                        uint32_t a0, uint32_t a1, uint32_t a2, uint32_t a3,
                                        uint32_t b0, uint32_t b1) {
    asm volatile("mma.sync.aligned.m16n8k16.row.col.f32.f16.f16.f32 "
                 "{%0,%1,%2,%3}, {%4,%5,%6,%7}, {%8,%9}, {%0,%1,%2,%3};"
                 : "+f"(c[0]), "+f"(c[1]), "+f"(c[2]), "+f"(c[3])
                 : "r"(a0), "r"(a1), "r"(a2), "r"(a3), "r"(b0), "r"(b1));
}

__device__ __forceinline__ bool load_mask(const void* m, int mode, size_t idx) {
    if (mode == 2) return ((const float*)m)[idx] != 0.0f;
    if (mode == 1) return ((const int*)m)[idx] != 0;
    return ((const unsigned char*)m)[idx] != 0u;
}

// ====================== GEMM tiling constants ===============================
// 256 threads = 8 warps (2m x 4n), warp tile 64x32. 2 CTAs/SM -> 16 warps/SM.
#define BM 128
#define BN 128
#define BK 32
#define NKT (DM_ / BK)        // 16
#define STG 3
#define SROWH 40              // halfs per smem row (80 bytes)
#define STG_BYTES (2 * BM * SROWH * 2)      // A+B per stage = 20480 B
#define GEMM_SMEM (STG * STG_BYTES)         // 61440 B
// O-phase smem layout (reuses stage memory after mainloop)
#define VPS 136               // vp_s stride in halfs
#define PS  72                // P_s stride in halfs
#define P_S_OFF (128 * VPS)   // halfs offset of P_s
// fp32 attn prefetch region (beyond pipeline stages; persistent)
#define PF_OFF  GEMM_SMEM                   // bytes; [64][64] f32 = 16384 B
#define AV_SMEM (GEMM_SMEM + 16384)         // 77824 B

// ============== fused GEMM1 + attnV:  vp = v@Wv^T;  O = P @ vp ==============
// CTA (bx, by): rows by*128 (= batches 2by, 2by+1), cols bx*128 (= head bx).
__global__ void __launch_bounds__(256, 2) hgemm_av(
    const __half* __restrict__ A, const __half* __restrict__ W,
    const float* __restrict__ attn_src, __half* __restrict__ O)
{
    extern __shared__ __half smh[];
    const uint32_t sbase = smem_u32(smh);
    const int tid = threadIdx.x;
    const int wid = tid >> 5, lane = tid & 31;
    const int gid = lane >> 2, tg = lane & 3;
    const int wm = wid >> 2, wn = wid & 3;
    const int bm = blockIdx.y * BM;
    const int bn = blockIdx.x * BN;
    const int lrow = tid >> 1;
    const int lch  = (tid & 1) * 16;

    float acc[4][4][4];
    #pragma unroll
    for (int i = 0; i < 4; i++)
        #pragma unroll
        for (int j = 0; j < 4; j++)
            #pragma unroll
            for (int r = 0; r < 4; r++) acc[i][j][r] = 0.f;

    const __half* ga0 = A + (size_t)(bm + lrow) * DM_ + lch;
    const __half* gb0 = W + (size_t)(bn + lrow) * DM_ + lch;
    auto load_tile = [&](int kt, int s) {
        uint32_t da = sbase + (uint32_t)(s * STG_BYTES)
                    + (uint32_t)lrow * (SROWH * 2) + (uint32_t)lch * 2;
        uint32_t db = da + BM * SROWH * 2;
        const __half* ga = ga0 + kt * BK;
        const __half* gb = gb0 + kt * BK;
        cp_async16(da,      ga);
        cp_async16(da + 16, ga + 8);
        cp_async16(db,      gb);
        cp_async16(db + 16, gb + 8);
    };
    const uint32_t aOff = (uint32_t)(wm * 64 + (lane & 15)) * (SROWH * 2)
                        + (uint32_t)(lane >> 4) * 16;
    const uint32_t bOff = (uint32_t)(BM * SROWH * 2)
        + (uint32_t)(wn * 32 + (lane & 7) + ((lane >> 4) << 3)) * (SROWH * 2)
        + (uint32_t)((lane >> 3) & 1) * 16;

    // ---- prefetch attn tile (fp32, 16 KB) as cp.async group 0 --------------
    {
        const int prow = tid >> 2;
        const int pb   = prow >> 5;
        const int pq   = prow & 31;
        const int cb   = (tid & 3) * 16;
        const float* src = attn_src
            + ((((size_t)blockIdx.x * B_ + (2 * blockIdx.y + pb)) * LQ_ + pq) * LK_) + cb;
        uint32_t dst = sbase + PF_OFF + (uint32_t)(prow * 64 + cb) * 4;
        cp_async16(dst,      src);
        cp_async16(dst + 16, src + 4);
        cp_async16(dst + 32, src + 8);
        cp_async16(dst + 48, src + 12);
    }
    CP_COMMIT();

    load_tile(0, 0); CP_COMMIT();
    load_tile(1, 1); CP_COMMIT();

    int stage = 0;
    for (int kt = 0; kt < NKT; kt++) {
        CP_WAIT1();
        __syncthreads();
        if (kt + 2 < NKT) load_tile(kt + 2, (kt + 2) % STG);
        CP_COMMIT();

        const uint32_t sa = sbase + (uint32_t)(stage * STG_BYTES);
        #pragma unroll
        for (int ks = 0; ks < 2; ks++) {
            uint32_t af[4][4];
            #pragma unroll
            for (int mt = 0; mt < 4; mt++)
                ldsm_x4(af[mt][0], af[mt][1], af[mt][2], af[mt][3],
                        sa + aOff + (uint32_t)(mt * 16 * SROWH * 2) + (uint32_t)(ks * 32));
            #pragma unroll
            for (int ntp = 0; ntp < 2; ntp++) {
                uint32_t b0, b1, b2, b3;
                ldsm_x4(b0, b1, b2, b3,
                        sa + bOff + (uint32_t)(ntp * 16 * SROWH * 2) + (uint32_t)(ks * 32));
                #pragma unroll
                for (int mt = 0; mt < 4; mt++) {
                    mma_f16(acc[mt][2 * ntp],     af[mt][0], af[mt][1], af[mt][2], af[mt][3], b0, b1);
                    mma_f16(acc[mt][2 * ntp + 1], af[mt][0], af[mt][1], af[mt][2], af[mt][3], b2, b3);
                }
            }
        }
        stage = (stage + 1 == STG) ? 0 : stage + 1;
    }
    asm volatile("cp.async.wait_group 0;" ::: "memory");
    __syncthreads();

    // ---- O phase: vp tile -> smem fp16; P from prefetched smem -> fp16 ------
    __half* vp_s = smh;             // [128][VPS]
    __half* P_s  = smh + P_S_OFF;   // [64][PS]

    #pragma unroll
    for (int mt = 0; mt < 4; mt++) {
        const int row = wm * 64 + mt * 16 + gid;
        #pragma unroll
        for (int nt = 0; nt < 4; nt++) {
            const int col = wn * 32 + nt * 8 + tg * 2;
            *(__half2*)(vp_s + row * VPS + col) =
                __floats2half2_rn(acc[mt][nt][0], acc[mt][nt][1]);
            *(__half2*)(vp_s + (row + 8) * VPS + col) =
                __floats2half2_rn(acc[mt][nt][2], acc[mt][nt][3]);
        }
    }

    // convert prefetched fp32 attn (smem) -> fp16 P_s
    {
        const int prow = tid >> 2;            // 0..63
        const int cb   = (tid & 3) * 16;
        const float* srcf = (const float*)((const char*)smh + PF_OFF) + prow * 64 + cb;
        #pragma unroll
        for (int j = 0; j < 4; j++) {
            float4 f = ((const float4*)srcf)[j];
            *(__half2*)(P_s + prow * PS + cb + j * 4)     = __floats2half2_rn(f.x, f.y);
            *(__half2*)(P_s + prow * PS + cb + j * 4 + 2) = __floats2half2_rn(f.z, f.w);
        }
    }
    __syncthreads();

    // ---- O = P_b(32x64) @ vp_b(64x128); warp: batch = wid>>2, quarter = wid&3
    const int wb = wid >> 2;
    const int wc = wid & 3;
    float oac[2][4][4];
    #pragma unroll
    for (int i = 0; i < 2; i++)
        #pragma unroll
        for (int j = 0; j < 4; j++)
            #pragma unroll
            for (int r = 0; r < 4; r++) oac[i][j][r] = 0.f;

    const uint32_t pbase  = sbase + (uint32_t)(P_S_OFF * 2);
    const uint32_t aOff2  = pbase
        + (uint32_t)(wb * 32 + (lane & 15)) * (PS * 2) + (uint32_t)(lane >> 4) * 16;
    const uint32_t bRow2  = (uint32_t)((lane & 7) + ((lane >> 3) & 1) * 8);
    const uint32_t bOff2  = sbase
        + (uint32_t)(wb * 64 + bRow2) * (VPS * 2)
        + (uint32_t)(wc * 32 + (lane >> 4) * 8) * 2;

    #pragma unroll
    for (int ks = 0; ks < 4; ks++) {
        uint32_t af[2][4];
        #pragma unroll
        for (int mt = 0; mt < 2; mt++)
            ldsm_x4(af[mt][0], af[mt][1], af[mt][2], af[mt][3],
                    aOff2 + (uint32_t)(mt * 16 * PS * 2) + (uint32_t)(ks * 32));
        #pragma unroll
        for (int ntp = 0; ntp < 2; ntp++) {
            uint32_t b0, b1, b2, b3;
            ldsm_x4_t(b0, b1, b2, b3,
                      bOff2 + (uint32_t)(ks * 16 * VPS * 2) + (uint32_t)(ntp * 16 * 2));
            #pragma unroll
            for (int mt = 0; mt < 2; mt++) {
                mma_f16(oac[mt][2 * ntp],     af[mt][0], af[mt][1], af[mt][2], af[mt][3], b0, b1);
                mma_f16(oac[mt][2 * ntp + 1], af[mt][0], af[mt][1], af[mt][2], af[mt][3], b2, b3);
            }
        }
    }

    {
        const size_t rb = ((size_t)(2 * blockIdx.y + wb)) * LQ_;
        #pragma unroll
        for (int mt = 0; mt < 2; mt++) {
            const int q0 = mt * 16 + gid;
            #pragma unroll
            for (int nt = 0; nt < 4; nt++) {
                const int col = blockIdx.x * BN + wc * 32 + nt * 8 + tg * 2;
                *(__half2*)(O + (rb + q0) * DM_ + col) =
                    __floats2half2_rn(oac[mt][nt][0], oac[mt][nt][1]);
                *(__half2*)(O + (rb + q0 + 8) * DM_ + col) =
                    __floats2half2_rn(oac[mt][nt][2], oac[mt][nt][3]);
            }
        }
    }
}

// ====================== plain fp16 GEMM (GEMM2) ==============================
__global__ void __launch_bounds__(256, 2) hgemm(
    const __half* __restrict__ A, const __half* __restrict__ W,
    __half* __restrict__ C)
{
    extern __shared__ __half smh[];
    const uint32_t sbase = smem_u32(smh);
    const int tid = threadIdx.x;
    const int wid = tid >> 5, lane = tid & 31;
    const int gid = lane >> 2, tg = lane & 3;
    const int wm = wid >> 2, wn = wid & 3;
    const int bm = blockIdx.y * BM;
    const int bn = blockIdx.x * BN;
    const int lrow = tid >> 1;
    const int lch  = (tid & 1) * 16;

    float acc[4][4][4];
    #pragma unroll
    for (int i = 0; i < 4; i++)
        #pragma unroll
        for (int j = 0; j < 4; j++)
            #pragma unroll
            for (int r = 0; r < 4; r++) acc[i][j][r] = 0.f;

    const __half* ga0 = A + (size_t)(bm + lrow) * DM_ + lch;
    const __half* gb0 = W + (size_t)(bn + lrow) * DM_ + lch;
    auto load_tile = [&](int kt, int s) {
        uint32_t da = sbase + (uint32_t)(s * STG_BYTES)
                    + (uint32_t)lrow * (SROWH * 2) + (uint32_t)lch * 2;
        uint32_t db = da + BM * SROWH * 2;
        const __half* ga = ga0 + kt * BK;
        const __half* gb = gb0 + kt * BK;
        cp_async16(da,      ga);
        cp_async16(da + 16, ga + 8);
        cp_async16(db,      gb);
        cp_async16(db + 16, gb + 8);
    };
    const uint32_t aOff = (uint32_t)(wm * 64 + (lane & 15)) * (SROWH * 2)
                        + (uint32_t)(lane >> 4) * 16;
    const uint32_t bOff = (uint32_t)(BM * SROWH * 2)
        + (uint32_t)(wn * 32 + (lane & 7) + ((lane >> 4) << 3)) * (SROWH * 2)
        + (uint32_t)((lane >> 3) & 1) * 16;

    load_tile(0, 0); CP_COMMIT();
    load_tile(1, 1); CP_COMMIT();
    int stage = 0;
    for (int kt = 0; kt < NKT; kt++) {
        CP_WAIT1();
        __syncthreads();
        if (kt + 2 < NKT) load_tile(kt + 2, (kt + 2) % STG);
        CP_COMMIT();

        const uint32_t sa = sbase + (uint32_t)(stage * STG_BYTES);
        #pragma unroll
        for (int ks = 0; ks < 2; ks++) {
            uint32_t af[4][4];
            #pragma unroll
            for (int mt = 0; mt < 4; mt++)
                ldsm_x4(af[mt][0], af[mt][1], af[mt][2], af[mt][3],
                        sa + aOff + (uint32_t)(mt * 16 * SROWH * 2) + (uint32_t)(ks * 32));
            #pragma unroll
            for (int ntp = 0; ntp < 2; ntp++) {
                uint32_t b0, b1, b2, b3;
                ldsm_x4(b0, b1, b2, b3,
                        sa + bOff + (uint32_t)(ntp * 16 * SROWH * 2) + (uint32_t)(ks * 32));
                #pragma unroll
                for (int mt = 0; mt < 4; mt++) {
                    mma_f16(acc[mt][2 * ntp],     af[mt][0], af[mt][1], af[mt][2], af[mt][3], b0, b1);
                    mma_f16(acc[mt][2 * ntp + 1], af[mt][0], af[mt][1], af[mt][2], af[mt][3], b2, b3);
                }
            }
        }
        stage = (stage + 1 == STG) ? 0 : stage + 1;
    }

    #pragma unroll
    for (int mt = 0; mt < 4; mt++) {
        const int row0 = bm + wm * 64 + mt * 16 + gid;
        #pragma unroll
        for (int nt = 0; nt < 4; nt++) {
            const int col0 = bn + wn * 32 + nt * 8 + tg * 2;
            *(__half2*)(C + (size_t)row0 * DM_ + col0) =
                __floats2half2_rn(acc[mt][nt][0], acc[mt][nt][1]);
            *(__half2*)(C + (size_t)(row0 + 8) * DM_ + col0) =
                __floats2half2_rn(acc[mt][nt][2], acc[mt][nt][3]);
        }
    }
}

// ---------------- fp32 -> fp16 converters -----------------------------------
__global__ void conv_f2h_kernel(const float* __restrict__ src,
                                __half* __restrict__ dst, size_t n) {
    size_t i = ((size_t)blockIdx.x * blockDim.x + threadIdx.x) * 8;
    if (i >= n) return;
    float4 f0 = *(const float4*)(src + i);
    float4 f1 = *(const float4*)(src + i + 4);
    __half2 h[4];
    h[0] = __floats2half2_rn(f0.x, f0.y);
    h[1] = __floats2half2_rn(f0.z, f0.w);
    h[2] = __floats2half2_rn(f1.x, f1.y);
    h[3] = __floats2half2_rn(f1.z, f1.w);
    *(uint4*)(dst + i) = *(uint4*)h;
}

// -------- effective map weights (warp-per-output) + mask detect -------------
__global__ void weff_detect_kernel(const float* __restrict__ Wq,
                                   const float* __restrict__ Wk,
                                   const float* __restrict__ Wmap,
                                   const unsigned char* __restrict__ m) {
    if (blockIdx.x == 512) {
        __shared__ int f0, f1;
        if (threadIdx.x == 0) { f0 = 0; f1 = 0; }
        __syncthreads();
        int lf = 0, lb = 0;
        for (int i = threadIdx.x; i < 4096; i += blockDim.x) {
            unsigned char c = m[i];
            if (c == 0x3Fu || c == 0x80u) lf = 1;
            if (c != 0u && (i & 3) != 0) lb = 1;
        }
        if (lf) atomicOr(&f0, 1);
        if (lb) atomicOr(&f1, 1);
        __syncthreads();
        if (threadIdx.x == 0) g_maskmode = f0 ? 2 : (f1 ? 0 : 1);
        return;
    }
    const int tid = threadIdx.x;
    const int wid = tid >> 5, lane = tid & 31;
    const int t = blockIdx.x * 8 + wid;
    const int isK = t >= H_ * DM_;
    const int r = isK ? (t - H_ * DM_) : t;
    const int h = r / DM_, dm = r % DM_;
    const float* W  = isK ? Wk : Wq;
    const float* wm = Wmap + (isK ? DK_ : 0);
    const float* Wp = W + (size_t)(h * DK_) * DM_ + dm;
    float s = 0.f;
    #pragma unroll
    for (int d4 = 0; d4 < 4; d4++) {
        const int d = lane + d4 * 32;
        s += wm[d] * Wp[(size_t)d * DM_];
    }
    #pragma unroll
    for (int o = 16; o; o >>= 1) s += __shfl_xor_sync(0xffffffffu, s, o);
    if (lane == 0) {
        if (isK) g_wkeff[r] = s; else g_wqeff[r] = s;
    }
}

// -------- fused scores + softmax + attn write (2 batches per block) ---------
__global__ __launch_bounds__(256) void attn_kernel(
    const float* __restrict__ qin, const float* __restrict__ kin,
    const void* __restrict__ mask, float* __restrict__ attn_buf)
{
    __shared__ float wS[2 * H_ * DM_];
    __shared__ float sqS[2 * H_ * LQ_];   // [pb][h][q]
    __shared__ float skS[2 * H_ * LK_];   // [pb][h][k]
    const int b0 = blockIdx.x * 2;
    const int tid = threadIdx.x, warp = tid >> 5, lane = tid & 31;

    for (int i = tid; i < H_ * DM_; i += 256) {
        wS[i]            = g_wqeff[i];
        wS[H_ * DM_ + i] = g_wkeff[i];
    }
    __syncthreads();

    for (int j = warp; j < 2 * (LQ_ + LK_); j += 8) {
        const int pb = j / 96, r = j % 96;
        const int b = b0 + pb;
        const float* vec;
        const float* wf;
        if (r < LQ_) { vec = qin + ((size_t)b * LQ_ + r) * DM_;          wf = wS; }
        else         { vec = kin + ((size_t)b * LK_ + (r - LQ_)) * DM_;  wf = wS + H_ * DM_; }
        const float4* v4 = (const float4*)vec;
        const float4* w0 = (const float4*)(wf);
        const float4* w1 = (const float4*)(wf + DM_);
        const float4* w2 = (const float4*)(wf + 2 * DM_);
        const float4* w3 = (const float4*)(wf + 3 * DM_);
        float s0 = 0.f, s1 = 0.f, s2 = 0.f, s3 = 0.f;
        #pragma unroll
        for (int it = 0; it < 4; it++) {
            const int idx = lane + it * 32;
            float4 x = v4[idx];
            float4 a0 = w0[idx];
            s0 += x.x * a0.x + x.y * a0.y + x.z * a0.z + x.w * a0.w;
            float4 a1 = w1[idx];
            s1 += x.x * a1.x + x.y * a1.y + x.z * a1.z + x.w * a1.w;
            float4 a2 = w2[idx];
            s2 += x.x * a2.x + x.y * a2.y + x.z * a2.z + x.w * a2.w;
            float4 a3 = w3[idx];
            s3 += x.x * a3.x + x.y * a3.y + x.z * a3.z + x.w * a3.w;
        }
        #pragma unroll
        for (int o = 16; o; o >>= 1) {
            s0 += __shfl_xor_sync(0xffffffffu, s0, o);
            s1 += __shfl_xor_sync(0xffffffffu, s1, o);
            s2 += __shfl_xor_sync(0xffffffffu, s2, o);
            s3 += __shfl_xor_sync(0xffffffffu, s3, o);
        }
        if (lane == 0) {
            if (r < LQ_) {
                float* sq = sqS + pb * H_ * LQ_;
                sq[0 * LQ_ + r] = s0; sq[1 * LQ_ + r] = s1;
                sq[2 * LQ_ + r] = s2; sq[3 * LQ_ + r] = s3;
            } else {
                const int kk = r - LQ_;
                float* sk = skS + pb * H_ * LK_;
                sk[0 * LK_ + kk] = s0; sk[1 * LK_ + kk] = s1;
                sk[2 * LK_ + kk] = s2; sk[3 * LK_ + kk] = s3;
            }
        }
    }
    __syncthreads();

    const int mm = g_maskmode;
    for (int rr = warp; rr < 2 * H_ * LQ_; rr += 8) {
        const int pb = rr >> 7;
        const int r  = rr & 127;
        const int h = r >> 5, qq = r & 31;
        const int b = b0 + pb;
        const float sq = sqS[pb * H_ * LQ_ + r];
        const float* sk = skS + pb * H_ * LK_ + h * LK_;
        const size_t mbase = ((size_t)b * LQ_ + qq) * LK_;
        bool m0 = load_mask(mask, mm, mbase + lane);
        bool m1 = load_mask(mask, mm, mbase + lane + 32);
        float v0 = m0 ? -1e10f : sq + sk[lane];
        float v1 = m1 ? -1e10f : sq + sk[lane + 32];
        float mx = fmaxf(v0, v1);
        #pragma unroll
        for (int o = 16; o; o >>= 1) mx = fmaxf(mx, __shfl_xor_sync(0xffffffffu, mx, o));
        float p0 = expf(v0 - mx), p1 = expf(v1 - mx);
        float sm = p0 + p1;
        #pragma unroll
        for (int o = 16; o; o >>= 1) sm += __shfl_xor_sync(0xffffffffu, sm, o);
        float inv = 1.0f / sm;
        p0 *= inv; p1 *= inv;
        const size_t ob = (((size_t)h * B_ + b) * LQ_ + qq) * LK_;
        attn_buf[ob + lane]      = p0;
        attn_buf[ob + lane + 32] = p1;
    }
}

// ---------------- bias + leakyReLU + residual + LayerNorm (vectorized) -----
__global__ __launch_bounds__(128) void epilogue_kernel(
    const float* __restrict__ qin, const float* __restrict__ fcb,
    const float* __restrict__ gamma, const float* __restrict__ beta,
    float* __restrict__ out)
{
    const int row = blockIdx.x;
    const int tid = threadIdx.x;
    const int j0  = tid * 4;
    __shared__ float rs[8];

    uint2 hraw = *(const uint2*)(g_fch + (size_t)row * DM_ + j0);
    const __half2* hp = (const __half2*)&hraw;
    float2 fa = __half22float2(hp[0]);
    float2 fb = __half22float2(hp[1]);
    float4 qv = *(const float4*)(qin + (size_t)row * DM_ + j0);
    float4 bv = *(const float4*)(fcb + j0);

    float y[4];
    float xs[4] = { fa.x + bv.x, fa.y + bv.y, fb.x + bv.z, fb.y + bv.w };
    float qf[4] = { qv.x, qv.y, qv.z, qv.w };
    float s = 0.f, s2 = 0.f;
    #pragma unroll
    for (int i = 0; i < 4; i++) {
        float x = xs[i];
        x = (x >= 0.f) ? x : 0.2f * x;
        x += qf[i];
        y[i] = x; s += x; s2 += x * x;
    }
    #pragma unroll
    for (int o = 16; o; o >>= 1) {
        s  += __shfl_xor_sync(0xffffffffu, s, o);
        s2 += __shfl_xor_sync(0xffffffffu, s2, o);
    }
    const int warp = tid >> 5, lane = tid & 31;
    if (lane == 0) { rs[warp] = s; rs[4 + warp] = s2; }
    __syncthreads();
    s  = rs[0] + rs[1] + rs[2] + rs[3];
    s2 = rs[4] + rs[5] + rs[6] + rs[7];
    const float mu  = s * (1.0f / DM_);
    const float var = s2 * (1.0f / DM_) - mu * mu;
    const float inv = rsqrtf(var + 1e-5f);

    float4 gv = *(const float4*)(gamma + j0);
    float4 bt = *(const float4*)(beta + j0);
    float4 ov;
    ov.x = gv.x * (y[0] - mu) * inv + bt.x;
    ov.y = gv.y * (y[1] - mu) * inv + bt.y;
    ov.z = gv.z * (y[2] - mu) * inv + bt.z;
    ov.w = gv.w * (y[3] - mu) * inv + bt.w;
    *(float4*)(out + (size_t)row * DM_ + j0) = ov;
}

// ---------------- launch ----------------------------------------------------
extern "C" void kernel_launch(void* const* d_in, const int* in_sizes, int n_in,
                              void* d_out, int out_size)
{
    const float* q    = (const float*)d_in[0];
    const float* k    = (const float*)d_in[1];
    const float* v    = (const float*)d_in[2];
    const void*  mask =               d_in[3];
    const float* Wq   = (const float*)d_in[4];
    const float* Wk   = (const float*)d_in[5];
    const float* Wv   = (const float*)d_in[6];
    const float* Wmap = (const float*)d_in[7];
    const float* fcW  = (const float*)d_in[8];
    const float* fcb  = (const float*)d_in[9];
    const float* gma  = (const float*)d_in[10];
    const float* bta  = (const float*)d_in[11];
    float* out = (float*)d_out;

    const size_t out_elems  = (size_t)B_ * LQ_ * DM_;
    const size_t attn_elems = (size_t)H_ * B_ * LQ_ * LK_;
    int write_attn = ((size_t)out_size >= out_elems + attn_elems) ? 1 : 0;

    void *p_vh = nullptr, *p_wvh = nullptr, *p_fcwh = nullptr;
    void *p_oh = nullptr, *p_fch = nullptr, *p_attn = nullptr;
    cudaGetSymbolAddress(&p_vh, g_vh);
    cudaGetSymbolAddress(&p_wvh, g_wvh);
    cudaGetSymbolAddress(&p_fcwh, g_fcwh);
    cudaGetSymbolAddress(&p_oh, g_oh);
    cudaGetSymbolAddress(&p_fch, g_fch);
    cudaGetSymbolAddress(&p_attn, g_attn);

    float* attn_buf = write_attn ? (out + out_elems) : (float*)p_attn;

    cudaFuncSetAttribute(hgemm_av, cudaFuncAttributeMaxDynamicSharedMemorySize, AV_SMEM);
    cudaFuncSetAttribute(hgemm, cudaFuncAttributeMaxDynamicSharedMemorySize, GEMM_SMEM);

    static cudaStream_t s1 = nullptr;
    static cudaEvent_t evFork = nullptr, evJoin = nullptr;
    if (s1 == nullptr) {
        cudaStreamCreateWithFlags(&s1, cudaStreamNonBlocking);
        cudaEventCreateWithFlags(&evFork, cudaEventDisableTiming);
        cudaEventCreateWithFlags(&evJoin, cudaEventDisableTiming);
    }

    cudaEventRecord(evFork, 0);
    cudaStreamWaitEvent(s1, evFork, 0);
    {
        size_t nv = (size_t)B_ * LK_ * DM_;
        conv_f2h_kernel<<<(unsigned)(nv / (256 * 8)), 256, 0, s1>>>(v, (__half*)p_vh, nv);
        size_t nw = (size_t)DM_ * DM_;
        conv_f2h_kernel<<<(unsigned)(nw / (256 * 8)), 256, 0, s1>>>(Wv, (__half*)p_wvh, nw);
        conv_f2h_kernel<<<(unsigned)(nw / (256 * 8)), 256, 0, s1>>>(fcW, (__half*)p_fcwh, nw);
    }
    cudaEventRecord(evJoin, s1);

    weff_detect_kernel<<<513, 256>>>(Wq, Wk, Wmap, (const unsigned char*)mask);
    attn_kernel<<<B_ / 2, 256>>>(q, k, mask, attn_buf);

    cudaStreamWaitEvent(0, evJoin, 0);

    // fused: vp = v@Wv^T (per-tile) then O = attn @ vp  -> g_oh (fp16)
    {
        dim3 grid(DM_ / BN, (B_ * LK_) / BM);   // (4, 512)
        hgemm_av<<<grid, 256, AV_SMEM>>>((const __half*)p_vh, (const __half*)p_wvh,
                                         attn_buf, (__half*)p_oh);
    }

    // fc = oattn @ fcW^T -> g_fch (fp16)
    {
        dim3 grid(DM_ / BN, (B_ * LQ_) / BM);   // (4, 256)
        hgemm<<<grid, 256, GEMM_SMEM>>>((const __half*)p_oh, (const __half*)p_fcwh,
                                        (__half*)p_fch);
    }

    epilogue_kernel<<<B_ * LQ_, 128>>>(q, fcb, gma, bta, out);
}

// round 16
// speedup vs baseline: 1.0932x; 1.0106x over previous
#include <cuda_runtime.h>
#include <cuda_fp16.h>
#include <cstdint>
#include <cstddef>

// Problem constants
#define H_    4
#define DM_   512
#define DK_   128
#define B_    1024
#define LQ_   32
#define LK_   64

// ---------------- scratch (device globals; no allocation allowed) ----------
__device__ float g_wqeff[H_ * DM_];
__device__ float g_wkeff[H_ * DM_];
__device__ float g_attn[(size_t)H_ * B_ * LQ_ * LK_];            //  33 MB (fallback)
__device__ __align__(16) __half g_ph[(size_t)H_ * (B_/2) * 64 * 64]; // 17 MB fp16 attn tiles
__device__ __align__(16) __half g_vh[(size_t)B_ * LK_ * DM_];    //  67 MB (v fp16)
__device__ __align__(16) __half g_wvh[DM_ * DM_];                // 0.5 MB
__device__ __align__(16) __half g_fcwh[DM_ * DM_];               // 0.5 MB
__device__ __align__(16) __half g_oh[(size_t)B_ * LQ_ * DM_];    //  33 MB (oattn fp16)
__device__ __align__(16) __half g_fch[(size_t)B_ * LQ_ * DM_];   //  33 MB (fc out fp16)
__device__ int   g_maskmode;

__device__ __forceinline__ uint32_t smem_u32(const void* p) {
    uint32_t a;
    asm("{ .reg .u64 t; cvta.to.shared.u64 t, %1; cvt.u32.u64 %0, t; }"
        : "=r"(a) : "l"(p));
    return a;
}
__device__ __forceinline__ void cp_async16(uint32_t dst, const void* src) {
    asm volatile("cp.async.cg.shared.global [%0], [%1], 16;" :: "r"(dst), "l"(src));
}
#define CP_COMMIT() asm volatile("cp.async.commit_group;" ::: "memory")
#define CP_WAIT1()  asm volatile("cp.async.wait_group 1;" ::: "memory")

__device__ __forceinline__ void ldsm_x4(uint32_t& r0, uint32_t& r1, uint32_t& r2,
                                        uint32_t& r3, uint32_t addr) {
    asm volatile("ldmatrix.sync.aligned.m8n8.x4.shared.b16 {%0,%1,%2,%3}, [%4];"
                 : "=r"(r0), "=r"(r1), "=r"(r2), "=r"(r3) : "r"(addr));
}
__device__ __forceinline__ void ldsm_x4_t(uint32_t& r0, uint32_t& r1, uint32_t& r2,
                                          uint32_t& r3, uint32_t addr) {
    asm volatile("ldmatrix.sync.aligned.m8n8.x4.trans.shared.b16 {%0,%1,%2,%3}, [%4];"
                 : "=r"(r0), "=r"(r1), "=r"(r2), "=r"(r3) : "r"(addr));
}
__device__ __forceinline__ void mma_f16(float* c,
                                        uint32_t a0, uint32_t a1, uint32_t a2, uint32_t a3,
                                        uint32_t b0, uint32_t b1) {
    asm volatile("mma.sync.aligned.m16n8k16.row.col.f32.f16.f16.f32 "
                 "{%0,%1,%2,%3}, {%4,%5,%6,%7}, {%8,%9}, {%0,%1,%2,%3};"
                 : "+f"(c[0]), "+f"(c[1]), "+f"(c[2]), "+f"(c[3])
                 : "r"(a0), "r"(a1), "r"(a2), "r"(a3), "r"(b0), "r"(b1));
}

__device__ __forceinline__ bool load_mask(const void* m, int mode, size_t idx) {
    if (mode == 2) return ((const float*)m)[idx] != 0.0f;
    if (mode == 1) return ((const int*)m)[idx] != 0;
    return ((const unsigned char*)m)[idx] != 0u;
}

// ====================== GEMM tiling constants ===============================
// 256 threads = 8 warps (2m x 4n), warp tile 64x32. 2 CTAs/SM -> 16 warps/SM.
#define BM 128
#define BN 128
#define BK 32
#define NKT (DM_ / BK)        // 16
#define STG 3
#define SROWH 40              // halfs per smem row (80 bytes)
#define STG_BYTES (2 * BM * SROWH * 2)      // A+B per stage = 20480 B
#define GEMM_SMEM (STG * STG_BYTES)         // 61440 B
// O-phase smem layout (reuses stage memory after mainloop)
#define VPS 136               // vp_s stride in halfs
#define PS  72                // P row stride in halfs (144 B), ldsm conflict-free
// persistent fp16 attn tile region (beyond pipeline stages): 64 rows x 144 B
#define PF_OFF  GEMM_SMEM                   // bytes; 64*144 = 9216 B used
#define AV_SMEM (GEMM_SMEM + 16384)         // 77824 B

// ============== fused GEMM1 + attnV:  vp = v@Wv^T;  O = P @ vp ==============
// CTA (bx, by): rows by*128 (= batches 2by, 2by+1), cols bx*128 (= head bx).
__global__ void __launch_bounds__(256, 2) hgemm_av(
    const __half* __restrict__ A, const __half* __restrict__ W,
    const __half* __restrict__ Pg, __half* __restrict__ O)
{
    extern __shared__ __half smh[];
    const uint32_t sbase = smem_u32(smh);
    const int tid = threadIdx.x;
    const int wid = tid >> 5, lane = tid & 31;
    const int gid = lane >> 2, tg = lane & 3;
    const int wm = wid >> 2, wn = wid & 3;
    const int bm = blockIdx.y * BM;
    const int bn = blockIdx.x * BN;
    const int lrow = tid >> 1;
    const int lch  = (tid & 1) * 16;

    float acc[4][4][4];
    #pragma unroll
    for (int i = 0; i < 4; i++)
        #pragma unroll
        for (int j = 0; j < 4; j++)
            #pragma unroll
            for (int r = 0; r < 4; r++) acc[i][j][r] = 0.f;

    const __half* ga0 = A + (size_t)(bm + lrow) * DM_ + lch;
    const __half* gb0 = W + (size_t)(bn + lrow) * DM_ + lch;
    auto load_tile = [&](int kt, int s) {
        uint32_t da = sbase + (uint32_t)(s * STG_BYTES)
                    + (uint32_t)lrow * (SROWH * 2) + (uint32_t)lch * 2;
        uint32_t db = da + BM * SROWH * 2;
        const __half* ga = ga0 + kt * BK;
        const __half* gb = gb0 + kt * BK;
        cp_async16(da,      ga);
        cp_async16(da + 16, ga + 8);
        cp_async16(db,      gb);
        cp_async16(db + 16, gb + 8);
    };
    const uint32_t aOff = (uint32_t)(wm * 64 + (lane & 15)) * (SROWH * 2)
                        + (uint32_t)(lane >> 4) * 16;
    const uint32_t bOff = (uint32_t)(BM * SROWH * 2)
        + (uint32_t)(wn * 32 + (lane & 7) + ((lane >> 4) << 3)) * (SROWH * 2)
        + (uint32_t)((lane >> 3) & 1) * 16;

    // ---- prefetch fp16 attn tile (8 KB) straight into ldsm layout (group 0) --
    {
        const int rr = tid >> 2;              // 0..63 (pb*32+qq)
        const int c4 = tid & 3;               // chunk pair selector
        const __half* src = Pg
            + (((size_t)blockIdx.x * (B_ / 2) + blockIdx.y) * 64 + rr) * 64;
        uint32_t dst = sbase + PF_OFF + (uint32_t)rr * (PS * 2);
        cp_async16(dst + (uint32_t)c4 * 16,       src + c4 * 8);
        cp_async16(dst + (uint32_t)(c4 + 4) * 16, src + (c4 + 4) * 8);
    }
    CP_COMMIT();

    load_tile(0, 0); CP_COMMIT();
    load_tile(1, 1); CP_COMMIT();

    int stage = 0;
    for (int kt = 0; kt < NKT; kt++) {
        CP_WAIT1();
        __syncthreads();
        if (kt + 2 < NKT) load_tile(kt + 2, (kt + 2) % STG);
        CP_COMMIT();

        const uint32_t sa = sbase + (uint32_t)(stage * STG_BYTES);
        #pragma unroll
        for (int ks = 0; ks < 2; ks++) {
            uint32_t af[4][4];
            #pragma unroll
            for (int mt = 0; mt < 4; mt++)
                ldsm_x4(af[mt][0], af[mt][1], af[mt][2], af[mt][3],
                        sa + aOff + (uint32_t)(mt * 16 * SROWH * 2) + (uint32_t)(ks * 32));
            #pragma unroll
            for (int ntp = 0; ntp < 2; ntp++) {
                uint32_t b0, b1, b2, b3;
                ldsm_x4(b0, b1, b2, b3,
                        sa + bOff + (uint32_t)(ntp * 16 * SROWH * 2) + (uint32_t)(ks * 32));
                #pragma unroll
                for (int mt = 0; mt < 4; mt++) {
                    mma_f16(acc[mt][2 * ntp],     af[mt][0], af[mt][1], af[mt][2], af[mt][3], b0, b1);
                    mma_f16(acc[mt][2 * ntp + 1], af[mt][0], af[mt][1], af[mt][2], af[mt][3], b2, b3);
                }
            }
        }
        stage = (stage + 1 == STG) ? 0 : stage + 1;
    }
    asm volatile("cp.async.wait_group 0;" ::: "memory");
    __syncthreads();

    // ---- O phase: vp tile -> smem fp16 (stage memory reused); P in PF -------
    __half* vp_s = smh;             // [128][VPS]

    #pragma unroll
    for (int mt = 0; mt < 4; mt++) {
        const int row = wm * 64 + mt * 16 + gid;
        #pragma unroll
        for (int nt = 0; nt < 4; nt++) {
            const int col = wn * 32 + nt * 8 + tg * 2;
            *(__half2*)(vp_s + row * VPS + col) =
                __floats2half2_rn(acc[mt][nt][0], acc[mt][nt][1]);
            *(__half2*)(vp_s + (row + 8) * VPS + col) =
                __floats2half2_rn(acc[mt][nt][2], acc[mt][nt][3]);
        }
    }
    __syncthreads();

    // ---- O = P_b(32x64) @ vp_b(64x128); warp: batch = wid>>2, quarter = wid&3
    const int wb = wid >> 2;
    const int wc = wid & 3;
    float oac[2][4][4];
    #pragma unroll
    for (int i = 0; i < 2; i++)
        #pragma unroll
        for (int j = 0; j < 4; j++)
            #pragma unroll
            for (int r = 0; r < 4; r++) oac[i][j][r] = 0.f;

    const uint32_t aOff2  = sbase + (uint32_t)PF_OFF
        + (uint32_t)(wb * 32 + (lane & 15)) * (PS * 2) + (uint32_t)(lane >> 4) * 16;
    const uint32_t bRow2  = (uint32_t)((lane & 7) + ((lane >> 3) & 1) * 8);
    const uint32_t bOff2  = sbase
        + (uint32_t)(wb * 64 + bRow2) * (VPS * 2)
        + (uint32_t)(wc * 32 + (lane >> 4) * 8) * 2;

    #pragma unroll
    for (int ks = 0; ks < 4; ks++) {
        uint32_t af[2][4];
        #pragma unroll
        for (int mt = 0; mt < 2; mt++)
            ldsm_x4(af[mt][0], af[mt][1], af[mt][2], af[mt][3],
                    aOff2 + (uint32_t)(mt * 16 * PS * 2) + (uint32_t)(ks * 32));
        #pragma unroll
        for (int ntp = 0; ntp < 2; ntp++) {
            uint32_t b0, b1, b2, b3;
            ldsm_x4_t(b0, b1, b2, b3,
                      bOff2 + (uint32_t)(ks * 16 * VPS * 2) + (uint32_t)(ntp * 16 * 2));
            #pragma unroll
            for (int mt = 0; mt < 2; mt++) {
                mma_f16(oac[mt][2 * ntp],     af[mt][0], af[mt][1], af[mt][2], af[mt][3], b0, b1);
                mma_f16(oac[mt][2 * ntp + 1], af[mt][0], af[mt][1], af[mt][2], af[mt][3], b2, b3);
            }
        }
    }

    {
        const size_t rb = ((size_t)(2 * blockIdx.y + wb)) * LQ_;
        #pragma unroll
        for (int mt = 0; mt < 2; mt++) {
            const int q0 = mt * 16 + gid;
            #pragma unroll
            for (int nt = 0; nt < 4; nt++) {
                const int col = blockIdx.x * BN + wc * 32 + nt * 8 + tg * 2;
                *(__half2*)(O + (rb + q0) * DM_ + col) =
                    __floats2half2_rn(oac[mt][nt][0], oac[mt][nt][1]);
                *(__half2*)(O + (rb + q0 + 8) * DM_ + col) =
                    __floats2half2_rn(oac[mt][nt][2], oac[mt][nt][3]);
            }
        }
    }
}

// ====================== plain fp16 GEMM (GEMM2) ==============================
__global__ void __launch_bounds__(256, 2) hgemm(
    const __half* __restrict__ A, const __half* __restrict__ W,
    __half* __restrict__ C)
{
    extern __shared__ __half smh[];
    const uint32_t sbase = smem_u32(smh);
    const int tid = threadIdx.x;
    const int wid = tid >> 5, lane = tid & 31;
    const int gid = lane >> 2, tg = lane & 3;
    const int wm = wid >> 2, wn = wid & 3;
    const int bm = blockIdx.y * BM;
    const int bn = blockIdx.x * BN;
    const int lrow = tid >> 1;
    const int lch  = (tid & 1) * 16;

    float acc[4][4][4];
    #pragma unroll
    for (int i = 0; i < 4; i++)
        #pragma unroll
        for (int j = 0; j < 4; j++)
            #pragma unroll
            for (int r = 0; r < 4; r++) acc[i][j][r] = 0.f;

    const __half* ga0 = A + (size_t)(bm + lrow) * DM_ + lch;
    const __half* gb0 = W + (size_t)(bn + lrow) * DM_ + lch;
    auto load_tile = [&](int kt, int s) {
        uint32_t da = sbase + (uint32_t)(s * STG_BYTES)
                    + (uint32_t)lrow * (SROWH * 2) + (uint32_t)lch * 2;
        uint32_t db = da + BM * SROWH * 2;
        const __half* ga = ga0 + kt * BK;
        const __half* gb = gb0 + kt * BK;
        cp_async16(da,      ga);
        cp_async16(da + 16, ga + 8);
        cp_async16(db,      gb);
        cp_async16(db + 16, gb + 8);
    };
    const uint32_t aOff = (uint32_t)(wm * 64 + (lane & 15)) * (SROWH * 2)
                        + (uint32_t)(lane >> 4) * 16;
    const uint32_t bOff = (uint32_t)(BM * SROWH * 2)
        + (uint32_t)(wn * 32 + (lane & 7) + ((lane >> 4) << 3)) * (SROWH * 2)
        + (uint32_t)((lane >> 3) & 1) * 16;

    load_tile(0, 0); CP_COMMIT();
    load_tile(1, 1); CP_COMMIT();
    int stage = 0;
    for (int kt = 0; kt < NKT; kt++) {
        CP_WAIT1();
        __syncthreads();
        if (kt + 2 < NKT) load_tile(kt + 2, (kt + 2) % STG);
        CP_COMMIT();

        const uint32_t sa = sbase + (uint32_t)(stage * STG_BYTES);
        #pragma unroll
        for (int ks = 0; ks < 2; ks++) {
            uint32_t af[4][4];
            #pragma unroll
            for (int mt = 0; mt < 4; mt++)
                ldsm_x4(af[mt][0], af[mt][1], af[mt][2], af[mt][3],
                        sa + aOff + (uint32_t)(mt * 16 * SROWH * 2) + (uint32_t)(ks * 32));
            #pragma unroll
            for (int ntp = 0; ntp < 2; ntp++) {
                uint32_t b0, b1, b2, b3;
                ldsm_x4(b0, b1, b2, b3,
                        sa + bOff + (uint32_t)(ntp * 16 * SROWH * 2) + (uint32_t)(ks * 32));
                #pragma unroll
                for (int mt = 0; mt < 4; mt++) {
                    mma_f16(acc[mt][2 * ntp],     af[mt][0], af[mt][1], af[mt][2], af[mt][3], b0, b1);
                    mma_f16(acc[mt][2 * ntp + 1], af[mt][0], af[mt][1], af[mt][2], af[mt][3], b2, b3);
                }
            }
        }
        stage = (stage + 1 == STG) ? 0 : stage + 1;
    }

    #pragma unroll
    for (int mt = 0; mt < 4; mt++) {
        const int row0 = bm + wm * 64 + mt * 16 + gid;
        #pragma unroll
        for (int nt = 0; nt < 4; nt++) {
            const int col0 = bn + wn * 32 + nt * 8 + tg * 2;
            *(__half2*)(C + (size_t)row0 * DM_ + col0) =
                __floats2half2_rn(acc[mt][nt][0], acc[mt][nt][1]);
            *(__half2*)(C + (size_t)(row0 + 8) * DM_ + col0) =
                __floats2half2_rn(acc[mt][nt][2], acc[mt][nt][3]);
        }
    }
}

// ---------------- fp32 -> fp16 converters -----------------------------------
__global__ void conv_f2h_kernel(const float* __restrict__ src,
                                __half* __restrict__ dst, size_t n) {
    size_t i = ((size_t)blockIdx.x * blockDim.x + threadIdx.x) * 8;
    if (i >= n) return;
    float4 f0 = *(const float4*)(src + i);
    float4 f1 = *(const float4*)(src + i + 4);
    __half2 h[4];
    h[0] = __floats2half2_rn(f0.x, f0.y);
    h[1] = __floats2half2_rn(f0.z, f0.w);
    h[2] = __floats2half2_rn(f1.x, f1.y);
    h[3] = __floats2half2_rn(f1.z, f1.w);
    *(uint4*)(dst + i) = *(uint4*)h;
}

// -------- effective map weights (warp-per-output) + mask detect -------------
__global__ void weff_detect_kernel(const float* __restrict__ Wq,
                                   const float* __restrict__ Wk,
                                   const float* __restrict__ Wmap,
                                   const unsigned char* __restrict__ m) {
    if (blockIdx.x == 512) {
        __shared__ int f0, f1;
        if (threadIdx.x == 0) { f0 = 0; f1 = 0; }
        __syncthreads();
        int lf = 0, lb = 0;
        for (int i = threadIdx.x; i < 4096; i += blockDim.x) {
            unsigned char c = m[i];
            if (c == 0x3Fu || c == 0x80u) lf = 1;
            if (c != 0u && (i & 3) != 0) lb = 1;
        }
        if (lf) atomicOr(&f0, 1);
        if (lb) atomicOr(&f1, 1);
        __syncthreads();
        if (threadIdx.x == 0) g_maskmode = f0 ? 2 : (f1 ? 0 : 1);
        return;
    }
    const int tid = threadIdx.x;
    const int wid = tid >> 5, lane = tid & 31;
    const int t = blockIdx.x * 8 + wid;
    const int isK = t >= H_ * DM_;
    const int r = isK ? (t - H_ * DM_) : t;
    const int h = r / DM_, dm = r % DM_;
    const float* W  = isK ? Wk : Wq;
    const float* wm = Wmap + (isK ? DK_ : 0);
    const float* Wp = W + (size_t)(h * DK_) * DM_ + dm;
    float s = 0.f;
    #pragma unroll
    for (int d4 = 0; d4 < 4; d4++) {
        const int d = lane + d4 * 32;
        s += wm[d] * Wp[(size_t)d * DM_];
    }
    #pragma unroll
    for (int o = 16; o; o >>= 1) s += __shfl_xor_sync(0xffffffffu, s, o);
    if (lane == 0) {
        if (isK) g_wkeff[r] = s; else g_wqeff[r] = s;
    }
}

// ---------------- fused scores + softmax + attn write ----------------------
__global__ __launch_bounds__(256) void attn_kernel(
    const float* __restrict__ qin, const float* __restrict__ kin,
    const void* __restrict__ mask, float* __restrict__ attn_buf,
    __half* __restrict__ Pg)
{
    __shared__ float wS[2 * H_ * DM_];
    __shared__ float sqS[H_ * LQ_];
    __shared__ float skS[H_ * LK_];
    const int b = blockIdx.x;
    const int tid = threadIdx.x, warp = tid >> 5, lane = tid & 31;

    for (int i = tid; i < H_ * DM_; i += 256) {
        wS[i]            = g_wqeff[i];
        wS[H_ * DM_ + i] = g_wkeff[i];
    }
    __syncthreads();

    for (int j = warp; j < LQ_ + LK_; j += 8) {
        const float* vec;
        const float* wf;
        if (j < LQ_) { vec = qin + ((size_t)b * LQ_ + j) * DM_;         wf = wS; }
        else         { vec = kin + ((size_t)b * LK_ + (j - LQ_)) * DM_; wf = wS + H_ * DM_; }
        const float4* v4 = (const float4*)vec;
        const float4* w0 = (const float4*)(wf);
        const float4* w1 = (const float4*)(wf + DM_);
        const float4* w2 = (const float4*)(wf + 2 * DM_);
        const float4* w3 = (const float4*)(wf + 3 * DM_);
        float s0 = 0.f, s1 = 0.f, s2 = 0.f, s3 = 0.f;
        #pragma unroll
        for (int it = 0; it < 4; it++) {
            const int idx = lane + it * 32;
            float4 x = v4[idx];
            float4 a0 = w0[idx];
            s0 += x.x * a0.x + x.y * a0.y + x.z * a0.z + x.w * a0.w;
            float4 a1 = w1[idx];
            s1 += x.x * a1.x + x.y * a1.y + x.z * a1.z + x.w * a1.w;
            float4 a2 = w2[idx];
            s2 += x.x * a2.x + x.y * a2.y + x.z * a2.z + x.w * a2.w;
            float4 a3 = w3[idx];
            s3 += x.x * a3.x + x.y * a3.y + x.z * a3.z + x.w * a3.w;
        }
        #pragma unroll
        for (int o = 16; o; o >>= 1) {
            s0 += __shfl_xor_sync(0xffffffffu, s0, o);
            s1 += __shfl_xor_sync(0xffffffffu, s1, o);
            s2 += __shfl_xor_sync(0xffffffffu, s2, o);
            s3 += __shfl_xor_sync(0xffffffffu, s3, o);
        }
        if (lane == 0) {
            if (j < LQ_) {
                sqS[0 * LQ_ + j] = s0; sqS[1 * LQ_ + j] = s1;
                sqS[2 * LQ_ + j] = s2; sqS[3 * LQ_ + j] = s3;
            } else {
                int kk = j - LQ_;
                skS[0 * LK_ + kk] = s0; skS[1 * LK_ + kk] = s1;
                skS[2 * LK_ + kk] = s2; skS[3 * LK_ + kk] = s3;
            }
        }
    }
    __syncthreads();

    const int by = b >> 1, pb = b & 1;
    const int mm = g_maskmode;
    for (int r = warp; r < H_ * LQ_; r += 8) {
        const int h = r >> 5, qq = r & 31;
        const float sq = sqS[r];
        const size_t mbase = ((size_t)b * LQ_ + qq) * LK_;
        bool m0 = load_mask(mask, mm, mbase + lane);
        bool m1 = load_mask(mask, mm, mbase + lane + 32);
        float v0 = m0 ? -1e10f : sq + skS[h * LK_ + lane];
        float v1 = m1 ? -1e10f : sq + skS[h * LK_ + lane + 32];
        float mx = fmaxf(v0, v1);
        #pragma unroll
        for (int o = 16; o; o >>= 1) mx = fmaxf(mx, __shfl_xor_sync(0xffffffffu, mx, o));
        float p0 = expf(v0 - mx), p1 = expf(v1 - mx);
        float sm = p0 + p1;
        #pragma unroll
        for (int o = 16; o; o >>= 1) sm += __shfl_xor_sync(0xffffffffu, sm, o);
        float inv = 1.0f / sm;
        p0 *= inv; p1 *= inv;
        const size_t ob = (((size_t)h * B_ + b) * LQ_ + qq) * LK_;
        attn_buf[ob + lane]      = p0;
        attn_buf[ob + lane + 32] = p1;
        // fp16 tile-ordered copy for GEMM1's O-phase
        __half* pd = Pg + (((size_t)h * (B_ / 2) + by) * 64 + pb * 32 + qq) * 64;
        pd[lane]      = __float2half_rn(p0);
        pd[lane + 32] = __float2half_rn(p1);
    }
}

// ---------------- bias + leakyReLU + residual + LayerNorm (vectorized) -----
__global__ __launch_bounds__(128) void epilogue_kernel(
    const float* __restrict__ qin, const float* __restrict__ fcb,
    const float* __restrict__ gamma, const float* __restrict__ beta,
    float* __restrict__ out)
{
    const int row = blockIdx.x;
    const int tid = threadIdx.x;
    const int j0  = tid * 4;
    __shared__ float rs[8];

    uint2 hraw = *(const uint2*)(g_fch + (size_t)row * DM_ + j0);
    const __half2* hp = (const __half2*)&hraw;
    float2 fa = __half22float2(hp[0]);
    float2 fb = __half22float2(hp[1]);
    float4 qv = *(const float4*)(qin + (size_t)row * DM_ + j0);
    float4 bv = *(const float4*)(fcb + j0);

    float y[4];
    float xs[4] = { fa.x + bv.x, fa.y + bv.y, fb.x + bv.z, fb.y + bv.w };
    float qf[4] = { qv.x, qv.y, qv.z, qv.w };
    float s = 0.f, s2 = 0.f;
    #pragma unroll
    for (int i = 0; i < 4; i++) {
        float x = xs[i];
        x = (x >= 0.f) ? x : 0.2f * x;
        x += qf[i];
        y[i] = x; s += x; s2 += x * x;
    }
    #pragma unroll
    for (int o = 16; o; o >>= 1) {
        s  += __shfl_xor_sync(0xffffffffu, s, o);
        s2 += __shfl_xor_sync(0xffffffffu, s2, o);
    }
    const int warp = tid >> 5, lane = tid & 31;
    if (lane == 0) { rs[warp] = s; rs[4 + warp] = s2; }
    __syncthreads();
    s  = rs[0] + rs[1] + rs[2] + rs[3];
    s2 = rs[4] + rs[5] + rs[6] + rs[7];
    const float mu  = s * (1.0f / DM_);
    const float var = s2 * (1.0f / DM_) - mu * mu;
    const float inv = rsqrtf(var + 1e-5f);

    float4 gv = *(const float4*)(gamma + j0);
    float4 bt = *(const float4*)(beta + j0);
    float4 ov;
    ov.x = gv.x * (y[0] - mu) * inv + bt.x;
    ov.y = gv.y * (y[1] - mu) * inv + bt.y;
    ov.z = gv.z * (y[2] - mu) * inv + bt.z;
    ov.w = gv.w * (y[3] - mu) * inv + bt.w;
    *(float4*)(out + (size_t)row * DM_ + j0) = ov;
}

// ---------------- launch ----------------------------------------------------
extern "C" void kernel_launch(void* const* d_in, const int* in_sizes, int n_in,
                              void* d_out, int out_size)
{
    const float* q    = (const float*)d_in[0];
    const float* k    = (const float*)d_in[1];
    const float* v    = (const float*)d_in[2];
    const void*  mask =               d_in[3];
    const float* Wq   = (const float*)d_in[4];
    const float* Wk   = (const float*)d_in[5];
    const float* Wv   = (const float*)d_in[6];
    const float* Wmap = (const float*)d_in[7];
    const float* fcW  = (const float*)d_in[8];
    const float* fcb  = (const float*)d_in[9];
    const float* gma  = (const float*)d_in[10];
    const float* bta  = (const float*)d_in[11];
    float* out = (float*)d_out;

    const size_t out_elems  = (size_t)B_ * LQ_ * DM_;
    const size_t attn_elems = (size_t)H_ * B_ * LQ_ * LK_;
    int write_attn = ((size_t)out_size >= out_elems + attn_elems) ? 1 : 0;

    void *p_vh = nullptr, *p_wvh = nullptr, *p_fcwh = nullptr;
    void *p_oh = nullptr, *p_fch = nullptr, *p_attn = nullptr, *p_ph = nullptr;
    cudaGetSymbolAddress(&p_vh, g_vh);
    cudaGetSymbolAddress(&p_wvh, g_wvh);
    cudaGetSymbolAddress(&p_fcwh, g_fcwh);
    cudaGetSymbolAddress(&p_oh, g_oh);
    cudaGetSymbolAddress(&p_fch, g_fch);
    cudaGetSymbolAddress(&p_attn, g_attn);
    cudaGetSymbolAddress(&p_ph, g_ph);

    float* attn_buf = write_attn ? (out + out_elems) : (float*)p_attn;

    cudaFuncSetAttribute(hgemm_av, cudaFuncAttributeMaxDynamicSharedMemorySize, AV_SMEM);
    cudaFuncSetAttribute(hgemm, cudaFuncAttributeMaxDynamicSharedMemorySize, GEMM_SMEM);

    static cudaStream_t s1 = nullptr;
    static cudaEvent_t evFork = nullptr, evJoin = nullptr;
    if (s1 == nullptr) {
        cudaStreamCreateWithFlags(&s1, cudaStreamNonBlocking);
        cudaEventCreateWithFlags(&evFork, cudaEventDisableTiming);
        cudaEventCreateWithFlags(&evJoin, cudaEventDisableTiming);
    }

    cudaEventRecord(evFork, 0);
    cudaStreamWaitEvent(s1, evFork, 0);
    {
        size_t nv = (size_t)B_ * LK_ * DM_;
        conv_f2h_kernel<<<(unsigned)(nv / (256 * 8)), 256, 0, s1>>>(v, (__half*)p_vh, nv);
        size_t nw = (size_t)DM_ * DM_;
        conv_f2h_kernel<<<(unsigned)(nw / (256 * 8)), 256, 0, s1>>>(Wv, (__half*)p_wvh, nw);
        conv_f2h_kernel<<<(unsigned)(nw / (256 * 8)), 256, 0, s1>>>(fcW, (__half*)p_fcwh, nw);
    }
    cudaEventRecord(evJoin, s1);

    weff_detect_kernel<<<513, 256>>>(Wq, Wk, Wmap, (const unsigned char*)mask);
    attn_kernel<<<B_, 256>>>(q, k, mask, attn_buf, (__half*)p_ph);

    cudaStreamWaitEvent(0, evJoin, 0);

    // fused: vp = v@Wv^T (per-tile) then O = attn @ vp  -> g_oh (fp16)
    {
        dim3 grid(DM_ / BN, (B_ * LK_) / BM);   // (4, 512)
        hgemm_av<<<grid, 256, AV_SMEM>>>((const __half*)p_vh, (const __half*)p_wvh,
                                         (const __half*)p_ph, (__half*)p_oh);
    }

    // fc = oattn @ fcW^T -> g_fch (fp16)
    {
        dim3 grid(DM_ / BN, (B_ * LQ_) / BM);   // (4, 256)
        hgemm<<<grid, 256, GEMM_SMEM>>>((const __half*)p_oh, (const __half*)p_fcwh,
                                        (__half*)p_fch);
    }

    epilogue_kernel<<<B_ * LQ_, 128>>>(q, fcb, gma, bta, out);
}